// round 8
// baseline (speedup 1.0000x reference)
#include <cuda_runtime.h>
#include <cuda_bf16.h>
#include <math.h>

#define BB   32
#define HH   64
#define WW   64
#define CC   192
#define DIN  384
#define LL   4096   // HH*WW

// ---------------- scratch (device globals; no runtime alloc) ----------------
__device__ __nv_bfloat16 g_xn [(size_t)BB * LL * CC];     // layernormed x (bf16)
__device__ float g_gm [BB * LL];                          // per-pixel mean of xn
__device__ int   g_dir[BB];                               // direction per batch
__device__ __nv_bfloat16 g_h1 [(size_t)BB * LL * DIN];    // fc1 output (bf16)
__device__ __nv_bfloat16 g_w1b[DIN * CC];                 // fc1_w in bf16
__device__ __nv_bfloat16 g_w2b[CC * DIN];                 // fc2_w in bf16

__device__ __forceinline__ void cp16(void* dst, const void* src) {
    unsigned d = (unsigned)__cvta_generic_to_shared(dst);
    asm volatile("cp.async.ca.shared.global [%0], [%1], 16;" :: "r"(d), "l"(src));
}
__device__ __forceinline__ void cp_commit() {
    asm volatile("cp.async.commit_group;");
}
__device__ __forceinline__ void cp_wait0() {
    asm volatile("cp.async.wait_group 0;");
}
__device__ __forceinline__ void cp_wait1() {
    asm volatile("cp.async.wait_group 1;");
}

__device__ __forceinline__ void ldsm4(unsigned r[4], unsigned addr) {
    asm volatile("ldmatrix.sync.aligned.m8n8.x4.shared.b16 {%0,%1,%2,%3}, [%4];"
                 : "=r"(r[0]), "=r"(r[1]), "=r"(r[2]), "=r"(r[3]) : "r"(addr));
}

__device__ __forceinline__ void mma_bf16(float c[4], const unsigned a[4],
                                         unsigned b0, unsigned b1) {
    asm volatile(
        "mma.sync.aligned.m16n8k16.row.col.f32.bf16.bf16.f32 "
        "{%0,%1,%2,%3}, {%4,%5,%6,%7}, {%8,%9}, {%0,%1,%2,%3};"
        : "+f"(c[0]), "+f"(c[1]), "+f"(c[2]), "+f"(c[3])
        : "r"(a[0]), "r"(a[1]), "r"(a[2]), "r"(a[3]), "r"(b0), "r"(b1));
}

// ---------------------------- 1) LayerNorm (bf16 out) ------------------------
__global__ __launch_bounds__(256) void ln_kernel(const float* __restrict__ x,
                                                 const float* __restrict__ nw,
                                                 const float* __restrict__ nb) {
    int warp = (blockIdx.x * blockDim.x + threadIdx.x) >> 5;
    int lane = threadIdx.x & 31;
    if (warp >= BB * LL) return;
    const float* row = x + (size_t)warp * CC;

    float2 v[3];
    float s = 0.f;
#pragma unroll
    for (int i = 0; i < 3; i++) {
        v[i] = *(const float2*)(row + 2 * lane + 64 * i);
        s += v[i].x + v[i].y;
    }
#pragma unroll
    for (int o = 16; o; o >>= 1) s += __shfl_xor_sync(0xffffffffu, s, o);
    float mu = s * (1.f / CC);

    float q = 0.f;
#pragma unroll
    for (int i = 0; i < 3; i++) {
        float dx = v[i].x - mu, dy = v[i].y - mu;
        q += dx * dx + dy * dy;
    }
#pragma unroll
    for (int o = 16; o; o >>= 1) q += __shfl_xor_sync(0xffffffffu, q, o);
    float rsig = rsqrtf(q * (1.f / CC) + 1e-5f);

    float xs = 0.f;
    __nv_bfloat16* dst = g_xn + (size_t)warp * CC;
#pragma unroll
    for (int i = 0; i < 3; i++) {
        int c = 2 * lane + 64 * i;
        float ax = (v[i].x - mu) * rsig * nw[c] + nb[c];
        float ay = (v[i].y - mu) * rsig * nw[c + 1] + nb[c + 1];
        *(__nv_bfloat162*)(dst + c) = __float22bfloat162_rn(make_float2(ax, ay));
        xs += ax + ay;
    }
#pragma unroll
    for (int o = 16; o; o >>= 1) xs += __shfl_xor_sync(0xffffffffu, xs, o);
    if (lane == 0) g_gm[warp] = xs * (1.f / CC);
}

// ---------------------------- 2) Direction selector --------------------------
__device__ __forceinline__ int refl(int k) {
    return (k == 0) ? 1 : ((k == 65) ? 62 : (k - 1));
}

__global__ __launch_bounds__(256) void sel_kernel(const float* __restrict__ w1,
                                                  const float* __restrict__ b1,
                                                  const float* __restrict__ w2,
                                                  const float* __restrict__ b2) {
    __shared__ float sg[LL];
    __shared__ float red[256];
    __shared__ float sh_s;
    int b = blockIdx.x;
    int tid = threadIdx.x;
    for (int i = tid; i < LL; i += 256) sg[i] = g_gm[b * LL + i];
    __syncthreads();

    float ssh = 0.f;
    for (int t = tid; t < 66 * 64; t += 256) {
        int r = t >> 6, j = t & 63;
        int rr = refl(r);
        ssh += fabsf(sg[rr * 64 + refl(j + 2)] - sg[rr * 64 + refl(j)]);
    }
    float ssv = 0.f;
    for (int t = tid; t < 64 * 66; t += 256) {
        int i = t / 66, c = t % 66;
        int cc = refl(c);
        ssv += fabsf(sg[refl(i + 2) * 64 + cc] - sg[refl(i) * 64 + cc]);
    }

    red[tid] = ssh; __syncthreads();
    for (int s = 128; s > 0; s >>= 1) { if (tid < s) red[tid] += red[tid + s]; __syncthreads(); }
    if (tid == 0) sh_s = red[0] * (1.f / 4224.f);
    __syncthreads();
    red[tid] = ssv; __syncthreads();
    for (int s = 128; s > 0; s >>= 1) { if (tid < s) red[tid] += red[tid + s]; __syncthreads(); }
    if (tid == 0) {
        float sh = sh_s, sv = red[0] * (1.f / 4224.f);
        float sc[4] = { sh, sv, 0.5f * (sh + sv), fabsf(sh - sv) };
        float hid[16];
#pragma unroll
        for (int j = 0; j < 16; j++) {
            float a = b1[j];
#pragma unroll
            for (int k = 0; k < 4; k++) a += sc[k] * w1[j * 4 + k];
            hid[j] = fmaxf(a, 0.f);
        }
        int best = 0; float bv = -1e30f;
#pragma unroll
        for (int i = 0; i < 4; i++) {
            float a = b2[i];
#pragma unroll
            for (int j = 0; j < 16; j++) a += hid[j] * w2[i * 16 + j];
            if (a > bv) { bv = a; best = i; }
        }
        g_dir[b] = best;
    }
}

// -------------------- 2b) weights fp32 -> bf16 prep --------------------------
__global__ __launch_bounds__(256) void wcvt_kernel(const float* __restrict__ w1,
                                                   const float* __restrict__ w2) {
    int i = (blockIdx.x * blockDim.x + threadIdx.x) * 4;
    if (i >= DIN * CC) return;
    {
        float4 v = *(const float4*)(w1 + i);
        *(__nv_bfloat162*)(g_w1b + i) = __float22bfloat162_rn(make_float2(v.x, v.y));
        *(__nv_bfloat162*)(g_w1b + i + 2) = __float22bfloat162_rn(make_float2(v.z, v.w));
    }
    {
        float4 v = *(const float4*)(w2 + i);
        *(__nv_bfloat162*)(g_w2b + i) = __float22bfloat162_rn(make_float2(v.x, v.y));
        *(__nv_bfloat162*)(g_w2b + i + 2) = __float22bfloat162_rn(make_float2(v.z, v.w));
    }
}

// ---------------- GEMM1 geometry: BM=128 BN=192 BK=64, 768 thr, 3 stages -----
#define GRB  144                  // bytes per smem row (128B data + 16B pad)
#define GA_B (128 * GRB)
#define GB_B (192 * GRB)
#define GT_B (GA_B + GB_B)        // 46080/stage; x3 stages

__device__ __forceinline__ void g1_load(const __nv_bfloat16* __restrict__ xnb,
                                        int m0, int n0, int k0, int dir,
                                        int tid, char* smA, char* smB) {
#pragma unroll
    for (int i = 0; i < 2; i++) {
        int q = tid + i * 768;
        if (q < 1024) {
            int row = q >> 3, c8 = q & 7;
            int l = m0 + row;
            int pix;
            if (dir == 0)      pix = l;
            else if (dir == 3) pix = ((l & 63) << 6) + 63 - (l >> 6);
            else               pix = ((l & 63) << 6) + (l >> 6);
            cp16(smA + row * GRB + c8 * 16, xnb + (size_t)pix * CC + k0 + c8 * 8);
        }
    }
#pragma unroll
    for (int i = 0; i < 2; i++) {
        int q = tid + i * 768;
        int row = q >> 3, c8 = q & 7;
        cp16(smB + row * GRB + c8 * 16, g_w1b + (size_t)(n0 + row) * CC + k0 + c8 * 8);
    }
}

__global__ __launch_bounds__(768) void gemm1_tc(const float* __restrict__ b1) {
    extern __shared__ char sm1[];
    const int b  = blockIdx.z;
    const int m0 = blockIdx.x * 128;
    const int n0 = blockIdx.y * 192;
    const int dir = g_dir[b];
    const int tid = threadIdx.x, lane = tid & 31, wid = tid >> 5;
    const int mw = (wid & 3) * 32, nw = (wid >> 2) * 32;
    const __nv_bfloat16* xnb = g_xn + (size_t)b * LL * CC;
    const unsigned sbase = (unsigned)__cvta_generic_to_shared(sm1);

    const unsigned a_lo = (mw + (lane & 15)) * GRB + ((lane & 16) ? 16 : 0);
    const unsigned b_lo = (nw + (lane & 7) + ((lane & 16) ? 8 : 0)) * GRB
                          + ((lane & 8) ? 16 : 0);

    float c[2][4][4];
#pragma unroll
    for (int im = 0; im < 2; im++)
#pragma unroll
        for (int jn = 0; jn < 4; jn++)
#pragma unroll
            for (int t = 0; t < 4; t++) c[im][jn][t] = 0.f;

    g1_load(xnb, m0, n0, 0, dir, tid, sm1, sm1 + GA_B);
    cp_commit();
    g1_load(xnb, m0, n0, 64, dir, tid, sm1 + GT_B, sm1 + GT_B + GA_B);
    cp_commit();

    const int NS = CC / 64;   // 3
#pragma unroll 1
    for (int s = 0; s < NS; s++) {
        if (s == NS - 1) cp_wait0(); else cp_wait1();
        __syncthreads();
        if (s == 0) {
            char* An = sm1 + 2 * GT_B;
            g1_load(xnb, m0, n0, 128, dir, tid, An, An + GA_B);
            cp_commit();
        }
        unsigned Au = sbase + s * GT_B;
        unsigned Bu = Au + GA_B;
#pragma unroll
        for (int kk = 0; kk < 4; kk++) {
            unsigned af[2][4], bf[2][4];
            ldsm4(af[0], Au + a_lo + kk * 32);
            ldsm4(af[1], Au + a_lo + 16 * GRB + kk * 32);
            ldsm4(bf[0], Bu + b_lo + kk * 32);
            ldsm4(bf[1], Bu + b_lo + 16 * GRB + kk * 32);
#pragma unroll
            for (int im = 0; im < 2; im++)
#pragma unroll
                for (int jn = 0; jn < 4; jn++)
                    mma_bf16(c[im][jn], af[im],
                             bf[jn >> 1][(jn & 1) * 2], bf[jn >> 1][(jn & 1) * 2 + 1]);
        }
    }
#pragma unroll
    for (int im = 0; im < 2; im++) {
        int r0 = m0 + mw + im * 16 + (lane >> 2);
#pragma unroll
        for (int jn = 0; jn < 4; jn++) {
            int col = n0 + nw + jn * 8 + 2 * (lane & 3);
            float bx = __ldg(b1 + col), by = __ldg(b1 + col + 1);
            __nv_bfloat162 o0 = __float22bfloat162_rn(
                make_float2(c[im][jn][0] + bx, c[im][jn][1] + by));
            __nv_bfloat162 o1 = __float22bfloat162_rn(
                make_float2(c[im][jn][2] + bx, c[im][jn][3] + by));
            *(__nv_bfloat162*)(g_h1 + ((size_t)b * LL + r0) * DIN + col) = o0;
            *(__nv_bfloat162*)(g_h1 + ((size_t)b * LL + r0 + 8) * DIN + col) = o1;
        }
    }
}

// ------ GEMM2 with fused conv3+GELU prologue: out = x + gelu(conv(h1))@w2^T+b2
// A tile (128 x 384 bf16) built ONCE in smem; B staged (3 bufs) over K.
#define A2RB 784                  // bytes per A row (768B data + 16B pad)
#define A2_B (128 * A2RB)         // 100352
#define B2RB 144
#define B2_B (192 * B2RB)         // 27648; x3 = 82944; total 183296

__device__ __forceinline__ void ld8bf(const __nv_bfloat16* p, float v[8]) {
    uint4 u = *(const uint4*)p;
    float2 a = __bfloat1622float2(*reinterpret_cast<__nv_bfloat162*>(&u.x));
    float2 b = __bfloat1622float2(*reinterpret_cast<__nv_bfloat162*>(&u.y));
    float2 c = __bfloat1622float2(*reinterpret_cast<__nv_bfloat162*>(&u.z));
    float2 d = __bfloat1622float2(*reinterpret_cast<__nv_bfloat162*>(&u.w));
    v[0] = a.x; v[1] = a.y; v[2] = b.x; v[3] = b.y;
    v[4] = c.x; v[5] = c.y; v[6] = d.x; v[7] = d.y;
}

__device__ __forceinline__ void g2_loadB(int k0, int tid, char* smB) {
#pragma unroll
    for (int i = 0; i < 2; i++) {
        int q = tid + i * 768;
        int row = q >> 3, c8 = q & 7;
        cp16(smB + row * B2RB + c8 * 16, g_w2b + (size_t)row * DIN + k0 + c8 * 8);
    }
}

__global__ __launch_bounds__(768) void gemm2_tc(const float* __restrict__ cw,
                                                const float* __restrict__ cb,
                                                const float* __restrict__ b2,
                                                const float* __restrict__ x,
                                                float* __restrict__ out) {
    extern __shared__ char sm2[];
    char* smA = sm2;
    char* smB = sm2 + A2_B;
    const int b  = blockIdx.z;
    const int m0 = blockIdx.x * 128;
    const int tid = threadIdx.x, lane = tid & 31, wid = tid >> 5;
    const int mw = (wid & 3) * 32, nw = (wid >> 2) * 32;
    const unsigned sAu = (unsigned)__cvta_generic_to_shared(smA);
    const unsigned sBu = (unsigned)__cvta_generic_to_shared(smB);

    // kick off first two B stages
    g2_loadB(0, tid, smB);
    cp_commit();
    g2_loadB(64, tid, smB + B2_B);
    cp_commit();

    // ---- build A = gelu(conv3(h1)) for rows [m0, m0+128), all 384 channels --
    {
        int r = tid / 6, cg = tid % 6;       // 128 rows x 6 col-groups of 64
        int l = m0 + r;
        const __nv_bfloat16* hp = g_h1 + ((size_t)b * LL + l) * DIN + cg * 64;
        bool hm = (l > 0), hl = (l < LL - 1);
        char* arow = smA + r * A2RB + cg * 128;
#pragma unroll 2
        for (int c8 = 0; c8 < 8; c8++) {
            int d0 = cg * 64 + c8 * 8;
            float pv[8] = {0,0,0,0,0,0,0,0}, cv[8], nv[8] = {0,0,0,0,0,0,0,0};
            ld8bf(hp + c8 * 8, cv);
            if (hm) ld8bf(hp + c8 * 8 - DIN, pv);
            if (hl) ld8bf(hp + c8 * 8 + DIN, nv);
            // conv weights: 24 floats + 8 bias via vector loads
            float wv[24], bbv[8];
#pragma unroll
            for (int t = 0; t < 6; t++) {
                float4 f = __ldg((const float4*)(cw + d0 * 3) + t);
                wv[t * 4 + 0] = f.x; wv[t * 4 + 1] = f.y;
                wv[t * 4 + 2] = f.z; wv[t * 4 + 3] = f.w;
            }
#pragma unroll
            for (int t = 0; t < 2; t++) {
                float4 f = __ldg((const float4*)(cb + d0) + t);
                bbv[t * 4 + 0] = f.x; bbv[t * 4 + 1] = f.y;
                bbv[t * 4 + 2] = f.z; bbv[t * 4 + 3] = f.w;
            }
            unsigned o[4];
#pragma unroll
            for (int j = 0; j < 4; j++) {
                float v0 = pv[2*j] * wv[6*j] + cv[2*j] * wv[6*j+1]
                         + nv[2*j] * wv[6*j+2] + bbv[2*j];
                float v1 = pv[2*j+1] * wv[6*j+3] + cv[2*j+1] * wv[6*j+4]
                         + nv[2*j+1] * wv[6*j+5] + bbv[2*j+1];
                float g0 = 0.5f * v0 * (1.f + erff(v0 * 0.70710678118654752f));
                float g1 = 0.5f * v1 * (1.f + erff(v1 * 0.70710678118654752f));
                __nv_bfloat162 q = __float22bfloat162_rn(make_float2(g0, g1));
                o[j] = *reinterpret_cast<unsigned*>(&q);
            }
            *(uint4*)(arow + c8 * 16) = make_uint4(o[0], o[1], o[2], o[3]);
        }
    }

    const unsigned a_lo = (mw + (lane & 15)) * A2RB + ((lane & 16) ? 16 : 0);
    const unsigned b_lo = (nw + (lane & 7) + ((lane & 16) ? 8 : 0)) * B2RB
                          + ((lane & 8) ? 16 : 0);

    float c[2][4][4];
#pragma unroll
    for (int im = 0; im < 2; im++)
#pragma unroll
        for (int jn = 0; jn < 4; jn++)
#pragma unroll
            for (int t = 0; t < 4; t++) c[im][jn][t] = 0.f;

    const int NS = DIN / 64;   // 6
#pragma unroll 1
    for (int s = 0; s < NS; s++) {
        if (s == NS - 1) cp_wait0(); else cp_wait1();
        __syncthreads();      // publishes A (s=0) and B stage s; fences buf reuse
        if (s + 2 < NS) {
            g2_loadB((s + 2) * 64, tid, smB + ((s + 2) % 3) * B2_B);
            cp_commit();
        }
        unsigned Bu = sBu + (s % 3) * B2_B;
        unsigned Ak = sAu + s * 128;          // A column offset for this K-stage
#pragma unroll
        for (int kk = 0; kk < 4; kk++) {
            unsigned af[2][4], bf[2][4];
            ldsm4(af[0], Ak + a_lo + kk * 32);
            ldsm4(af[1], Ak + a_lo + 16 * A2RB + kk * 32);
            ldsm4(bf[0], Bu + b_lo + kk * 32);
            ldsm4(bf[1], Bu + b_lo + 16 * B2RB + kk * 32);
#pragma unroll
            for (int im = 0; im < 2; im++)
#pragma unroll
                for (int jn = 0; jn < 4; jn++)
                    mma_bf16(c[im][jn], af[im],
                             bf[jn >> 1][(jn & 1) * 2], bf[jn >> 1][(jn & 1) * 2 + 1]);
        }
    }
#pragma unroll
    for (int im = 0; im < 2; im++) {
        int r0 = m0 + mw + im * 16 + (lane >> 2);
#pragma unroll
        for (int jn = 0; jn < 4; jn++) {
            int col = nw + jn * 8 + 2 * (lane & 3);
            float bx = __ldg(b2 + col), by = __ldg(b2 + col + 1);
            size_t base0 = ((size_t)b * LL + r0) * CC + col;
            size_t base1 = ((size_t)b * LL + r0 + 8) * CC + col;
            float2 x0 = *(const float2*)(x + base0);
            float2 x1 = *(const float2*)(x + base1);
            float2 o0 = { c[im][jn][0] + bx + x0.x, c[im][jn][1] + by + x0.y };
            float2 o1 = { c[im][jn][2] + bx + x1.x, c[im][jn][3] + by + x1.y };
            *(float2*)(out + base0) = o0;
            *(float2*)(out + base1) = o1;
        }
    }
}

// ---------------------------------------------------------------------------
extern "C" void kernel_launch(void* const* d_in, const int* in_sizes, int n_in,
                              void* d_out, int out_size) {
    const float* x      = (const float*)d_in[0];
    const float* norm_w = (const float*)d_in[1];
    const float* norm_b = (const float*)d_in[2];
    const float* sel_w1 = (const float*)d_in[3];
    const float* sel_b1 = (const float*)d_in[4];
    const float* sel_w2 = (const float*)d_in[5];
    const float* sel_b2 = (const float*)d_in[6];
    const float* fc1_w  = (const float*)d_in[7];
    const float* fc1_b  = (const float*)d_in[8];
    const float* conv_w = (const float*)d_in[9];
    const float* conv_b = (const float*)d_in[10];
    const float* fc2_w  = (const float*)d_in[11];
    const float* fc2_b  = (const float*)d_in[12];
    float* out = (float*)d_out;

    cudaFuncSetAttribute(gemm1_tc, cudaFuncAttributeMaxDynamicSharedMemorySize,
                         3 * GT_B);
    cudaFuncSetAttribute(gemm2_tc, cudaFuncAttributeMaxDynamicSharedMemorySize,
                         A2_B + 3 * B2_B);

    ln_kernel<<<(BB * LL) / 8, 256>>>(x, norm_w, norm_b);
    sel_kernel<<<BB, 256>>>(sel_w1, sel_b1, sel_w2, sel_b2);
    wcvt_kernel<<<(DIN * CC / 4 + 255) / 256, 256>>>(fc1_w, fc2_w);
    gemm1_tc<<<dim3(LL / 128, DIN / 192, BB), 768, 3 * GT_B>>>(fc1_b);
    gemm2_tc<<<dim3(LL / 128, 1, BB), 768, A2_B + 3 * B2_B>>>(
        conv_w, conv_b, fc2_b, x, out);
}

// round 9
// speedup vs baseline: 1.2728x; 1.2728x over previous
#include <cuda_runtime.h>
#include <cuda_bf16.h>
#include <math.h>

#define BB   32
#define HH   64
#define WW   64
#define CC   192
#define DIN  384
#define LL   4096   // HH*WW

// ---------------- scratch (device globals; no runtime alloc) ----------------
__device__ __nv_bfloat16 g_xn [(size_t)BB * LL * CC];     // layernormed x (bf16)
__device__ float g_gm [BB * LL];                          // per-pixel mean of xn
__device__ int   g_dir[BB];                               // direction per batch
__device__ __nv_bfloat16 g_h1 [(size_t)BB * LL * DIN];    // fc1 output (bf16)
__device__ __nv_bfloat16 g_act[(size_t)BB * LL * DIN];    // gelu(conv(h1)) (bf16)
__device__ __nv_bfloat16 g_w1b[DIN * CC];                 // fc1_w in bf16
__device__ __nv_bfloat16 g_w2b[CC * DIN];                 // fc2_w in bf16

__device__ __forceinline__ void cp16(void* dst, const void* src) {
    unsigned d = (unsigned)__cvta_generic_to_shared(dst);
    asm volatile("cp.async.cg.shared.global [%0], [%1], 16;" :: "r"(d), "l"(src));
}
__device__ __forceinline__ void cp_commit() {
    asm volatile("cp.async.commit_group;");
}
__device__ __forceinline__ void cp_wait0() {
    asm volatile("cp.async.wait_group 0;");
}
__device__ __forceinline__ void cp_wait1() {
    asm volatile("cp.async.wait_group 1;");
}

__device__ __forceinline__ void ldsm4(unsigned r[4], unsigned addr) {
    asm volatile("ldmatrix.sync.aligned.m8n8.x4.shared.b16 {%0,%1,%2,%3}, [%4];"
                 : "=r"(r[0]), "=r"(r[1]), "=r"(r[2]), "=r"(r[3]) : "r"(addr));
}

__device__ __forceinline__ void mma_bf16(float c[4], const unsigned a[4],
                                         unsigned b0, unsigned b1) {
    asm volatile(
        "mma.sync.aligned.m16n8k16.row.col.f32.bf16.bf16.f32 "
        "{%0,%1,%2,%3}, {%4,%5,%6,%7}, {%8,%9}, {%0,%1,%2,%3};"
        : "+f"(c[0]), "+f"(c[1]), "+f"(c[2]), "+f"(c[3])
        : "r"(a[0]), "r"(a[1]), "r"(a[2]), "r"(a[3]), "r"(b0), "r"(b1));
}

// ---------------------------- 1) LayerNorm (bf16 out) ------------------------
__global__ __launch_bounds__(256) void ln_kernel(const float* __restrict__ x,
                                                 const float* __restrict__ nw,
                                                 const float* __restrict__ nb) {
    int warp = (blockIdx.x * blockDim.x + threadIdx.x) >> 5;
    int lane = threadIdx.x & 31;
    if (warp >= BB * LL) return;
    const float* row = x + (size_t)warp * CC;

    float2 v[3];
    float s = 0.f;
#pragma unroll
    for (int i = 0; i < 3; i++) {
        v[i] = *(const float2*)(row + 2 * lane + 64 * i);
        s += v[i].x + v[i].y;
    }
#pragma unroll
    for (int o = 16; o; o >>= 1) s += __shfl_xor_sync(0xffffffffu, s, o);
    float mu = s * (1.f / CC);

    float q = 0.f;
#pragma unroll
    for (int i = 0; i < 3; i++) {
        float dx = v[i].x - mu, dy = v[i].y - mu;
        q += dx * dx + dy * dy;
    }
#pragma unroll
    for (int o = 16; o; o >>= 1) q += __shfl_xor_sync(0xffffffffu, q, o);
    float rsig = rsqrtf(q * (1.f / CC) + 1e-5f);

    float xs = 0.f;
    __nv_bfloat16* dst = g_xn + (size_t)warp * CC;
#pragma unroll
    for (int i = 0; i < 3; i++) {
        int c = 2 * lane + 64 * i;
        float ax = (v[i].x - mu) * rsig * nw[c] + nb[c];
        float ay = (v[i].y - mu) * rsig * nw[c + 1] + nb[c + 1];
        *(__nv_bfloat162*)(dst + c) = __float22bfloat162_rn(make_float2(ax, ay));
        xs += ax + ay;
    }
#pragma unroll
    for (int o = 16; o; o >>= 1) xs += __shfl_xor_sync(0xffffffffu, xs, o);
    if (lane == 0) g_gm[warp] = xs * (1.f / CC);
}

// ---------------------------- 2) Direction selector --------------------------
__device__ __forceinline__ int refl(int k) {
    return (k == 0) ? 1 : ((k == 65) ? 62 : (k - 1));
}

__global__ __launch_bounds__(256) void sel_kernel(const float* __restrict__ w1,
                                                  const float* __restrict__ b1,
                                                  const float* __restrict__ w2,
                                                  const float* __restrict__ b2) {
    __shared__ float sg[LL];
    __shared__ float red[256];
    __shared__ float sh_s;
    int b = blockIdx.x;
    int tid = threadIdx.x;
    for (int i = tid; i < LL; i += 256) sg[i] = g_gm[b * LL + i];
    __syncthreads();

    float ssh = 0.f;
    for (int t = tid; t < 66 * 64; t += 256) {
        int r = t >> 6, j = t & 63;
        int rr = refl(r);
        ssh += fabsf(sg[rr * 64 + refl(j + 2)] - sg[rr * 64 + refl(j)]);
    }
    float ssv = 0.f;
    for (int t = tid; t < 64 * 66; t += 256) {
        int i = t / 66, c = t % 66;
        int cc = refl(c);
        ssv += fabsf(sg[refl(i + 2) * 64 + cc] - sg[refl(i) * 64 + cc]);
    }

    red[tid] = ssh; __syncthreads();
    for (int s = 128; s > 0; s >>= 1) { if (tid < s) red[tid] += red[tid + s]; __syncthreads(); }
    if (tid == 0) sh_s = red[0] * (1.f / 4224.f);
    __syncthreads();
    red[tid] = ssv; __syncthreads();
    for (int s = 128; s > 0; s >>= 1) { if (tid < s) red[tid] += red[tid + s]; __syncthreads(); }
    if (tid == 0) {
        float sh = sh_s, sv = red[0] * (1.f / 4224.f);
        float sc[4] = { sh, sv, 0.5f * (sh + sv), fabsf(sh - sv) };
        float hid[16];
#pragma unroll
        for (int j = 0; j < 16; j++) {
            float a = b1[j];
#pragma unroll
            for (int k = 0; k < 4; k++) a += sc[k] * w1[j * 4 + k];
            hid[j] = fmaxf(a, 0.f);
        }
        int best = 0; float bv = -1e30f;
#pragma unroll
        for (int i = 0; i < 4; i++) {
            float a = b2[i];
#pragma unroll
            for (int j = 0; j < 16; j++) a += hid[j] * w2[i * 16 + j];
            if (a > bv) { bv = a; best = i; }
        }
        g_dir[b] = best;
    }
}

// -------------------- 2b) weights fp32 -> bf16 prep --------------------------
__global__ __launch_bounds__(256) void wcvt_kernel(const float* __restrict__ w1,
                                                   const float* __restrict__ w2) {
    int i = (blockIdx.x * blockDim.x + threadIdx.x) * 4;
    if (i >= DIN * CC) return;
    {
        float4 v = *(const float4*)(w1 + i);
        *(__nv_bfloat162*)(g_w1b + i) = __float22bfloat162_rn(make_float2(v.x, v.y));
        *(__nv_bfloat162*)(g_w1b + i + 2) = __float22bfloat162_rn(make_float2(v.z, v.w));
    }
    {
        float4 v = *(const float4*)(w2 + i);
        *(__nv_bfloat162*)(g_w2b + i) = __float22bfloat162_rn(make_float2(v.x, v.y));
        *(__nv_bfloat162*)(g_w2b + i + 2) = __float22bfloat162_rn(make_float2(v.z, v.w));
    }
}

// ======================= GEMM1: BM=128 BN=192, K=192 =========================
// B (fc1_w tile, 192 rows x 192 bf16) preloaded ONCE; A staged 3x (BK=64).
// A row stride 144B (bank step 36%32=4, conflict-free; 16B-aligned).
// B row stride 400B (bank step 100%32=4, conflict-free; 16B-aligned).
#define A1RB 144
#define A1_S (128 * A1RB)         // 18432 per stage, x3
#define B1RB 400
#define B1_B (192 * B1RB)         // 76800
#define G1_SMEM (B1_B + 3 * A1_S) // 132096

__device__ __forceinline__ void g1_loadA(const __nv_bfloat16* __restrict__ xnb,
                                         int m0, int k0, int dir,
                                         int tid, char* smA) {
#pragma unroll
    for (int i = 0; i < 2; i++) {
        int q = tid + i * 768;
        if (q < 1024) {
            int row = q >> 3, c8 = q & 7;
            int l = m0 + row;
            int pix;
            if (dir == 0)      pix = l;
            else if (dir == 3) pix = ((l & 63) << 6) + 63 - (l >> 6);
            else               pix = ((l & 63) << 6) + (l >> 6);
            cp16(smA + row * A1RB + c8 * 16, xnb + (size_t)pix * CC + k0 + c8 * 8);
        }
    }
}

__global__ __launch_bounds__(768) void gemm1_tc(const float* __restrict__ b1) {
    extern __shared__ char sm1[];
    char* smB = sm1;
    char* smA = sm1 + B1_B;
    const int b  = blockIdx.z;
    const int m0 = blockIdx.x * 128;
    const int n0 = blockIdx.y * 192;
    const int dir = g_dir[b];
    const int tid = threadIdx.x, lane = tid & 31, wid = tid >> 5;
    const int mw = (wid & 3) * 32, nw = (wid >> 2) * 32;
    const __nv_bfloat16* xnb = g_xn + (size_t)b * LL * CC;
    const unsigned sAu = (unsigned)__cvta_generic_to_shared(smA);
    const unsigned sBu = (unsigned)__cvta_generic_to_shared(smB);

    // group0: whole B tile (192x192 bf16 = 24 x 16B per row) + A stage 0
    {
        // 192 rows * 24 chunks = 4608 = 768 * 6
#pragma unroll
        for (int i = 0; i < 6; i++) {
            int q = tid + i * 768;
            int row = q / 24, c = q % 24;
            cp16(smB + row * B1RB + c * 16, g_w1b + (size_t)(n0 + row) * CC + c * 8);
        }
        g1_loadA(xnb, m0, 0, dir, tid, smA);
        cp_commit();
        g1_loadA(xnb, m0, 64, dir, tid, smA + A1_S);
        cp_commit();
    }

    const unsigned a_lo = (mw + (lane & 15)) * A1RB + ((lane & 16) ? 16 : 0);
    const unsigned b_lo = (nw + (lane & 7) + ((lane & 16) ? 8 : 0)) * B1RB
                          + ((lane & 8) ? 16 : 0);

    float c[2][4][4];
#pragma unroll
    for (int im = 0; im < 2; im++)
#pragma unroll
        for (int jn = 0; jn < 4; jn++)
#pragma unroll
            for (int t = 0; t < 4; t++) c[im][jn][t] = 0.f;

    const int NS = CC / 64;   // 3
#pragma unroll 1
    for (int s = 0; s < NS; s++) {
        if (s == NS - 1) cp_wait0(); else cp_wait1();
        __syncthreads();
        if (s == 0) {
            g1_loadA(xnb, m0, 128, dir, tid, smA + 2 * A1_S);
            cp_commit();
        }
        unsigned Au = sAu + s * A1_S;
        unsigned Bk = sBu + s * 128;          // B column offset (64 bf16)
#pragma unroll
        for (int kk = 0; kk < 4; kk++) {
            unsigned af[2][4], bf[2][4];
            ldsm4(af[0], Au + a_lo + kk * 32);
            ldsm4(af[1], Au + a_lo + 16 * A1RB + kk * 32);
            ldsm4(bf[0], Bk + b_lo + kk * 32);
            ldsm4(bf[1], Bk + b_lo + 16 * B1RB + kk * 32);
#pragma unroll
            for (int im = 0; im < 2; im++)
#pragma unroll
                for (int jn = 0; jn < 4; jn++)
                    mma_bf16(c[im][jn], af[im],
                             bf[jn >> 1][(jn & 1) * 2], bf[jn >> 1][(jn & 1) * 2 + 1]);
        }
    }
#pragma unroll
    for (int im = 0; im < 2; im++) {
        int r0 = m0 + mw + im * 16 + (lane >> 2);
#pragma unroll
        for (int jn = 0; jn < 4; jn++) {
            int col = n0 + nw + jn * 8 + 2 * (lane & 3);
            float bx = __ldg(b1 + col), by = __ldg(b1 + col + 1);
            __nv_bfloat162 o0 = __float22bfloat162_rn(
                make_float2(c[im][jn][0] + bx, c[im][jn][1] + by));
            __nv_bfloat162 o1 = __float22bfloat162_rn(
                make_float2(c[im][jn][2] + bx, c[im][jn][3] + by));
            *(__nv_bfloat162*)(g_h1 + ((size_t)b * LL + r0) * DIN + col) = o0;
            *(__nv_bfloat162*)(g_h1 + ((size_t)b * LL + r0 + 8) * DIN + col) = o1;
        }
    }
}

// ---------------------------- 4) depthwise conv3 + GELU (bf16 io) -----------
__device__ __forceinline__ void ld4bf(const __nv_bfloat16* p, float v[4]) {
    uint2 u = *(const uint2*)p;
    float2 a = __bfloat1622float2(*reinterpret_cast<__nv_bfloat162*>(&u.x));
    float2 b = __bfloat1622float2(*reinterpret_cast<__nv_bfloat162*>(&u.y));
    v[0] = a.x; v[1] = a.y; v[2] = b.x; v[3] = b.y;
}

__global__ __launch_bounds__(384) void convgelu_kernel(const float* __restrict__ cw,
                                                       const float* __restrict__ cb) {
    const int b  = blockIdx.y;
    const int l0 = blockIdx.x * 128;
    const int tid = threadIdx.x;
    const int d4 = tid % 96;
    const int rg = tid / 96;
    const int ls = l0 + rg * 32;
    const int d0 = d4 * 4;

    float w0[4], w1[4], w2[4], bb[4];
#pragma unroll
    for (int j = 0; j < 4; j++) {
        w0[j] = __ldg(cw + (d0 + j) * 3 + 0);
        w1[j] = __ldg(cw + (d0 + j) * 3 + 1);
        w2[j] = __ldg(cw + (d0 + j) * 3 + 2);
        bb[j] = __ldg(cb + d0 + j);
    }

    const __nv_bfloat16* base = g_h1 + ((size_t)b * LL) * DIN + d0;
    __nv_bfloat16* obase = g_act + ((size_t)b * LL) * DIN + d0;

    float pv[4] = { 0, 0, 0, 0 }, cv[4], nv[4];
    if (ls != 0) ld4bf(base + (size_t)(ls - 1) * DIN, pv);
    ld4bf(base + (size_t)ls * DIN, cv);

#pragma unroll 4
    for (int i = 0; i < 32; i++) {
        int l = ls + i;
        if (l == LL - 1) { nv[0] = nv[1] = nv[2] = nv[3] = 0.f; }
        else ld4bf(base + (size_t)(l + 1) * DIN, nv);
        float o[4];
#pragma unroll
        for (int j = 0; j < 4; j++) {
            float v = pv[j] * w0[j] + cv[j] * w1[j] + nv[j] * w2[j] + bb[j];
            o[j] = 0.5f * v * (1.f + erff(v * 0.70710678118654752f));
        }
        __nv_bfloat162 q0 = __float22bfloat162_rn(make_float2(o[0], o[1]));
        __nv_bfloat162 q1 = __float22bfloat162_rn(make_float2(o[2], o[3]));
        uint2 st;
        st.x = *reinterpret_cast<unsigned*>(&q0);
        st.y = *reinterpret_cast<unsigned*>(&q1);
        *(uint2*)(obase + (size_t)l * DIN) = st;
#pragma unroll
        for (int j = 0; j < 4; j++) { pv[j] = cv[j]; cv[j] = nv[j]; }
    }
}

// ======================= GEMM2: BM=128 BN=192, K=384 =========================
// B = ENTIRE fc2_w (192 x 384 bf16) preloaded once; A staged 3x (BK=64).
// B row stride 784B (bank step 196%32=4, conflict-free; 16B-aligned).
#define A2RB 144
#define A2_S (128 * A2RB)         // 18432 per stage, x3
#define B2RB 784
#define B2_B (192 * B2RB)         // 150528
#define G2_SMEM (B2_B + 3 * A2_S) // 205824

__device__ __forceinline__ void g2_loadA(const __nv_bfloat16* __restrict__ act,
                                         int m0, int k0, int tid, char* smA) {
#pragma unroll
    for (int i = 0; i < 2; i++) {
        int q = tid + i * 768;
        if (q < 1024) {
            int row = q >> 3, c8 = q & 7;
            cp16(smA + row * A2RB + c8 * 16,
                 act + (size_t)(m0 + row) * DIN + k0 + c8 * 8);
        }
    }
}

__global__ __launch_bounds__(768) void gemm2_tc(const float* __restrict__ b2,
                                                const float* __restrict__ x,
                                                float* __restrict__ out) {
    extern __shared__ char sm2[];
    char* smB = sm2;
    char* smA = sm2 + B2_B;
    const int b  = blockIdx.z;
    const int m0 = blockIdx.x * 128;
    const int tid = threadIdx.x, lane = tid & 31, wid = tid >> 5;
    const int mw = (wid & 3) * 32, nw = (wid >> 2) * 32;
    const __nv_bfloat16* act = g_act + (size_t)b * LL * DIN;
    const unsigned sAu = (unsigned)__cvta_generic_to_shared(smA);
    const unsigned sBu = (unsigned)__cvta_generic_to_shared(smB);

    // group0: whole B (192 rows x 48 x 16B) + A stage 0
    {
#pragma unroll
        for (int i = 0; i < 12; i++) {
            int q = tid + i * 768;
            int row = q / 48, c = q % 48;
            cp16(smB + row * B2RB + c * 16, g_w2b + (size_t)row * DIN + c * 8);
        }
        g2_loadA(act, m0, 0, tid, smA);
        cp_commit();
        g2_loadA(act, m0, 64, tid, smA + A2_S);
        cp_commit();
    }

    const unsigned a_lo = (mw + (lane & 15)) * A2RB + ((lane & 16) ? 16 : 0);
    const unsigned b_lo = (nw + (lane & 7) + ((lane & 16) ? 8 : 0)) * B2RB
                          + ((lane & 8) ? 16 : 0);

    float c[2][4][4];
#pragma unroll
    for (int im = 0; im < 2; im++)
#pragma unroll
        for (int jn = 0; jn < 4; jn++)
#pragma unroll
            for (int t = 0; t < 4; t++) c[im][jn][t] = 0.f;

    const int NS = DIN / 64;   // 6
#pragma unroll 1
    for (int s = 0; s < NS; s++) {
        if (s == NS - 1) cp_wait0(); else cp_wait1();
        __syncthreads();
        if (s + 2 < NS) {
            g2_loadA(act, m0, (s + 2) * 64, tid, smA + ((s + 2) % 3) * A2_S);
            cp_commit();
        }
        unsigned Au = sAu + (s % 3) * A2_S;
        unsigned Bk = sBu + s * 128;          // B column offset (64 bf16)
#pragma unroll
        for (int kk = 0; kk < 4; kk++) {
            unsigned af[2][4], bf[2][4];
            ldsm4(af[0], Au + a_lo + kk * 32);
            ldsm4(af[1], Au + a_lo + 16 * A2RB + kk * 32);
            ldsm4(bf[0], Bk + b_lo + kk * 32);
            ldsm4(bf[1], Bk + b_lo + 16 * B2RB + kk * 32);
#pragma unroll
            for (int im = 0; im < 2; im++)
#pragma unroll
                for (int jn = 0; jn < 4; jn++)
                    mma_bf16(c[im][jn], af[im],
                             bf[jn >> 1][(jn & 1) * 2], bf[jn >> 1][(jn & 1) * 2 + 1]);
        }
    }
#pragma unroll
    for (int im = 0; im < 2; im++) {
        int r0 = m0 + mw + im * 16 + (lane >> 2);
#pragma unroll
        for (int jn = 0; jn < 4; jn++) {
            int col = nw + jn * 8 + 2 * (lane & 3);
            float bx = __ldg(b2 + col), by = __ldg(b2 + col + 1);
            size_t base0 = ((size_t)b * LL + r0) * CC + col;
            size_t base1 = ((size_t)b * LL + r0 + 8) * CC + col;
            float2 x0 = *(const float2*)(x + base0);
            float2 x1 = *(const float2*)(x + base1);
            float2 o0 = { c[im][jn][0] + bx + x0.x, c[im][jn][1] + by + x0.y };
            float2 o1 = { c[im][jn][2] + bx + x1.x, c[im][jn][3] + by + x1.y };
            *(float2*)(out + base0) = o0;
            *(float2*)(out + base1) = o1;
        }
    }
}

// ---------------------------------------------------------------------------
extern "C" void kernel_launch(void* const* d_in, const int* in_sizes, int n_in,
                              void* d_out, int out_size) {
    const float* x      = (const float*)d_in[0];
    const float* norm_w = (const float*)d_in[1];
    const float* norm_b = (const float*)d_in[2];
    const float* sel_w1 = (const float*)d_in[3];
    const float* sel_b1 = (const float*)d_in[4];
    const float* sel_w2 = (const float*)d_in[5];
    const float* sel_b2 = (const float*)d_in[6];
    const float* fc1_w  = (const float*)d_in[7];
    const float* fc1_b  = (const float*)d_in[8];
    const float* conv_w = (const float*)d_in[9];
    const float* conv_b = (const float*)d_in[10];
    const float* fc2_w  = (const float*)d_in[11];
    const float* fc2_b  = (const float*)d_in[12];
    float* out = (float*)d_out;

    cudaFuncSetAttribute(gemm1_tc, cudaFuncAttributeMaxDynamicSharedMemorySize,
                         G1_SMEM);
    cudaFuncSetAttribute(gemm2_tc, cudaFuncAttributeMaxDynamicSharedMemorySize,
                         G2_SMEM);

    ln_kernel<<<(BB * LL) / 8, 256>>>(x, norm_w, norm_b);
    sel_kernel<<<BB, 256>>>(sel_w1, sel_b1, sel_w2, sel_b2);
    wcvt_kernel<<<(DIN * CC / 4 + 255) / 256, 256>>>(fc1_w, fc2_w);
    gemm1_tc<<<dim3(LL / 128, DIN / 192, BB), 768, G1_SMEM>>>(fc1_b);
    convgelu_kernel<<<dim3(LL / 128, BB), 384>>>(conv_w, conv_b);
    gemm2_tc<<<dim3(LL / 128, 1, BB), 768, G2_SMEM>>>(fc2_b, x, out);
}

// round 12
// speedup vs baseline: 1.4818x; 1.1642x over previous
#include <cuda_runtime.h>
#include <cuda_bf16.h>
#include <math.h>

#define BB   32
#define HH   64
#define WW   64
#define CC   192
#define DIN  384
#define LL   4096   // HH*WW

// ---------------- scratch (device globals; no runtime alloc) ----------------
__device__ __nv_bfloat16 g_xn [(size_t)BB * LL * CC];     // layernormed x (bf16)
__device__ float g_gm [BB * LL];                          // per-pixel mean of xn
__device__ int   g_dir[BB];                               // direction per batch
__device__ __nv_bfloat16 g_h1 [(size_t)BB * LL * DIN];    // fc1 output (bf16)
__device__ __nv_bfloat16 g_act[(size_t)BB * LL * DIN];    // gelu(conv(h1)) (bf16)
__device__ __nv_bfloat16 g_w1b[DIN * CC];                 // fc1_w in bf16
__device__ __nv_bfloat16 g_w2b[CC * DIN];                 // fc2_w in bf16

__device__ __forceinline__ void cp16(void* dst, const void* src) {
    unsigned d = (unsigned)__cvta_generic_to_shared(dst);
    asm volatile("cp.async.cg.shared.global [%0], [%1], 16;" :: "r"(d), "l"(src));
}
__device__ __forceinline__ void cp_commit() {
    asm volatile("cp.async.commit_group;");
}
__device__ __forceinline__ void cp_wait0() {
    asm volatile("cp.async.wait_group 0;");
}

__device__ __forceinline__ void ldsm4(unsigned r[4], unsigned addr) {
    asm volatile("ldmatrix.sync.aligned.m8n8.x4.shared.b16 {%0,%1,%2,%3}, [%4];"
                 : "=r"(r[0]), "=r"(r[1]), "=r"(r[2]), "=r"(r[3]) : "r"(addr));
}

__device__ __forceinline__ void mma_bf16(float c[4], const unsigned a[4],
                                         unsigned b0, unsigned b1) {
    asm volatile(
        "mma.sync.aligned.m16n8k16.row.col.f32.bf16.bf16.f32 "
        "{%0,%1,%2,%3}, {%4,%5,%6,%7}, {%8,%9}, {%0,%1,%2,%3};"
        : "+f"(c[0]), "+f"(c[1]), "+f"(c[2]), "+f"(c[3])
        : "r"(a[0]), "r"(a[1]), "r"(a[2]), "r"(a[3]), "r"(b0), "r"(b1));
}

// ---------------------------- 1) LayerNorm (bf16 out) ------------------------
__global__ __launch_bounds__(256) void ln_kernel(const float* __restrict__ x,
                                                 const float* __restrict__ nw,
                                                 const float* __restrict__ nb) {
    int warp = (blockIdx.x * blockDim.x + threadIdx.x) >> 5;
    int lane = threadIdx.x & 31;
    if (warp >= BB * LL) return;
    const float* row = x + (size_t)warp * CC;

    float2 v[3];
    float s = 0.f;
#pragma unroll
    for (int i = 0; i < 3; i++) {
        v[i] = *(const float2*)(row + 2 * lane + 64 * i);
        s += v[i].x + v[i].y;
    }
#pragma unroll
    for (int o = 16; o; o >>= 1) s += __shfl_xor_sync(0xffffffffu, s, o);
    float mu = s * (1.f / CC);

    float q = 0.f;
#pragma unroll
    for (int i = 0; i < 3; i++) {
        float dx = v[i].x - mu, dy = v[i].y - mu;
        q += dx * dx + dy * dy;
    }
#pragma unroll
    for (int o = 16; o; o >>= 1) q += __shfl_xor_sync(0xffffffffu, q, o);
    float rsig = rsqrtf(q * (1.f / CC) + 1e-5f);

    float xs = 0.f;
    __nv_bfloat16* dst = g_xn + (size_t)warp * CC;
#pragma unroll
    for (int i = 0; i < 3; i++) {
        int c = 2 * lane + 64 * i;
        float ax = (v[i].x - mu) * rsig * nw[c] + nb[c];
        float ay = (v[i].y - mu) * rsig * nw[c + 1] + nb[c + 1];
        *(__nv_bfloat162*)(dst + c) = __float22bfloat162_rn(make_float2(ax, ay));
        xs += ax + ay;
    }
#pragma unroll
    for (int o = 16; o; o >>= 1) xs += __shfl_xor_sync(0xffffffffu, xs, o);
    if (lane == 0) g_gm[warp] = xs * (1.f / CC);
}

// ---------------------------- 2) Direction selector --------------------------
__device__ __forceinline__ int refl(int k) {
    return (k == 0) ? 1 : ((k == 65) ? 62 : (k - 1));
}

__global__ __launch_bounds__(256) void sel_kernel(const float* __restrict__ w1,
                                                  const float* __restrict__ b1,
                                                  const float* __restrict__ w2,
                                                  const float* __restrict__ b2) {
    __shared__ float sg[LL];
    __shared__ float red[256];
    __shared__ float sh_s;
    int b = blockIdx.x;
    int tid = threadIdx.x;
    for (int i = tid; i < LL; i += 256) sg[i] = g_gm[b * LL + i];
    __syncthreads();

    float ssh = 0.f;
    for (int t = tid; t < 66 * 64; t += 256) {
        int r = t >> 6, j = t & 63;
        int rr = refl(r);
        ssh += fabsf(sg[rr * 64 + refl(j + 2)] - sg[rr * 64 + refl(j)]);
    }
    float ssv = 0.f;
    for (int t = tid; t < 64 * 66; t += 256) {
        int i = t / 66, c = t % 66;
        int cc = refl(c);
        ssv += fabsf(sg[refl(i + 2) * 64 + cc] - sg[refl(i) * 64 + cc]);
    }

    red[tid] = ssh; __syncthreads();
    for (int s = 128; s > 0; s >>= 1) { if (tid < s) red[tid] += red[tid + s]; __syncthreads(); }
    if (tid == 0) sh_s = red[0] * (1.f / 4224.f);
    __syncthreads();
    red[tid] = ssv; __syncthreads();
    for (int s = 128; s > 0; s >>= 1) { if (tid < s) red[tid] += red[tid + s]; __syncthreads(); }
    if (tid == 0) {
        float sh = sh_s, sv = red[0] * (1.f / 4224.f);
        float sc[4] = { sh, sv, 0.5f * (sh + sv), fabsf(sh - sv) };
        float hid[16];
#pragma unroll
        for (int j = 0; j < 16; j++) {
            float a = b1[j];
#pragma unroll
            for (int k = 0; k < 4; k++) a += sc[k] * w1[j * 4 + k];
            hid[j] = fmaxf(a, 0.f);
        }
        int best = 0; float bv = -1e30f;
#pragma unroll
        for (int i = 0; i < 4; i++) {
            float a = b2[i];
#pragma unroll
            for (int j = 0; j < 16; j++) a += hid[j] * w2[i * 16 + j];
            if (a > bv) { bv = a; best = i; }
        }
        g_dir[b] = best;
    }
}

// -------------------- 2b) weights fp32 -> bf16 prep --------------------------
__global__ __launch_bounds__(256) void wcvt_kernel(const float* __restrict__ w1,
                                                   const float* __restrict__ w2) {
    int i = (blockIdx.x * blockDim.x + threadIdx.x) * 4;
    if (i >= DIN * CC) return;
    {
        float4 v = *(const float4*)(w1 + i);
        *(__nv_bfloat162*)(g_w1b + i) = __float22bfloat162_rn(make_float2(v.x, v.y));
        *(__nv_bfloat162*)(g_w1b + i + 2) = __float22bfloat162_rn(make_float2(v.z, v.w));
    }
    {
        float4 v = *(const float4*)(w2 + i);
        *(__nv_bfloat162*)(g_w2b + i) = __float22bfloat162_rn(make_float2(v.x, v.y));
        *(__nv_bfloat162*)(g_w2b + i + 2) = __float22bfloat162_rn(make_float2(v.z, v.w));
    }
}

// ---------------- GEMM geometry: row stride 144B, BK=64, 2-stage -------------
#define GRB 144

// ======================= GEMM1: BM=128 BN=128, 512 thr, 2 CTA/SM =============
#define G1A_B (128 * GRB)
#define G1B_B (128 * GRB)
#define G1T_B (G1A_B + G1B_B)     // 36864/stage, x2 = 73728

__device__ __forceinline__ void g1_load(const __nv_bfloat16* __restrict__ xnb,
                                        int m0, int n0, int k0, int dir,
                                        int tid, char* smA, char* smB) {
#pragma unroll
    for (int i = 0; i < 2; i++) {
        int q = tid + i * 512;
        int row = q >> 3, c8 = q & 7;
        int l = m0 + row;
        int pix;
        if (dir == 0)      pix = l;
        else if (dir == 3) pix = ((l & 63) << 6) + 63 - (l >> 6);
        else               pix = ((l & 63) << 6) + (l >> 6);
        cp16(smA + row * GRB + c8 * 16, xnb + (size_t)pix * CC + k0 + c8 * 8);
    }
#pragma unroll
    for (int i = 0; i < 2; i++) {
        int q = tid + i * 512;
        int row = q >> 3, c8 = q & 7;
        cp16(smB + row * GRB + c8 * 16, g_w1b + (size_t)(n0 + row) * CC + k0 + c8 * 8);
    }
}

__global__ __launch_bounds__(512, 2) void gemm1_tc(const float* __restrict__ b1) {
    extern __shared__ char sm1[];
    const int b  = blockIdx.z;
    const int m0 = blockIdx.x * 128;
    const int n0 = blockIdx.y * 128;
    const int dir = g_dir[b];
    const int tid = threadIdx.x, lane = tid & 31, wid = tid >> 5;
    const int mw = (wid & 3) * 32, nw = (wid >> 2) * 32;
    const __nv_bfloat16* xnb = g_xn + (size_t)b * LL * CC;
    const unsigned sbase = (unsigned)__cvta_generic_to_shared(sm1);

    const unsigned a_lo = (mw + (lane & 15)) * GRB + ((lane & 16) ? 16 : 0);
    const unsigned b_lo = (nw + (lane & 7) + ((lane & 16) ? 8 : 0)) * GRB
                          + ((lane & 8) ? 16 : 0);

    float c[2][4][4];
#pragma unroll
    for (int im = 0; im < 2; im++)
#pragma unroll
        for (int jn = 0; jn < 4; jn++)
#pragma unroll
            for (int t = 0; t < 4; t++) c[im][jn][t] = 0.f;

    g1_load(xnb, m0, n0, 0, dir, tid, sm1, sm1 + G1A_B);
    cp_commit();

    const int NS = CC / 64;   // 3
#pragma unroll 1
    for (int s = 0; s < NS; s++) {
        cp_wait0();
        __syncthreads();
        if (s + 1 < NS) {
            char* An = sm1 + ((s + 1) & 1) * G1T_B;
            g1_load(xnb, m0, n0, (s + 1) * 64, dir, tid, An, An + G1A_B);
            cp_commit();
        }
        unsigned Au = sbase + (s & 1) * G1T_B;
        unsigned Bu = Au + G1A_B;
#pragma unroll
        for (int kk = 0; kk < 4; kk++) {
            unsigned af[2][4], bf[2][4];
            ldsm4(af[0], Au + a_lo + kk * 32);
            ldsm4(af[1], Au + a_lo + 16 * GRB + kk * 32);
            ldsm4(bf[0], Bu + b_lo + kk * 32);
            ldsm4(bf[1], Bu + b_lo + 16 * GRB + kk * 32);
#pragma unroll
            for (int im = 0; im < 2; im++)
#pragma unroll
                for (int jn = 0; jn < 4; jn++)
                    mma_bf16(c[im][jn], af[im],
                             bf[jn >> 1][(jn & 1) * 2], bf[jn >> 1][(jn & 1) * 2 + 1]);
        }
        __syncthreads();
    }
#pragma unroll
    for (int im = 0; im < 2; im++) {
        int r0 = m0 + mw + im * 16 + (lane >> 2);
#pragma unroll
        for (int jn = 0; jn < 4; jn++) {
            int col = n0 + nw + jn * 8 + 2 * (lane & 3);
            float bx = __ldg(b1 + col), by = __ldg(b1 + col + 1);
            __nv_bfloat162 o0 = __float22bfloat162_rn(
                make_float2(c[im][jn][0] + bx, c[im][jn][1] + by));
            __nv_bfloat162 o1 = __float22bfloat162_rn(
                make_float2(c[im][jn][2] + bx, c[im][jn][3] + by));
            *(__nv_bfloat162*)(g_h1 + ((size_t)b * LL + r0) * DIN + col) = o0;
            *(__nv_bfloat162*)(g_h1 + ((size_t)b * LL + r0 + 8) * DIN + col) = o1;
        }
    }
}

// ---------------------------- 4) depthwise conv3 + GELU (bf16 io) -----------
__device__ __forceinline__ void ld4bf(const __nv_bfloat16* p, float v[4]) {
    uint2 u = *(const uint2*)p;
    float2 a = __bfloat1622float2(*reinterpret_cast<__nv_bfloat162*>(&u.x));
    float2 b = __bfloat1622float2(*reinterpret_cast<__nv_bfloat162*>(&u.y));
    v[0] = a.x; v[1] = a.y; v[2] = b.x; v[3] = b.y;
}

__global__ __launch_bounds__(384) void convgelu_kernel(const float* __restrict__ cw,
                                                       const float* __restrict__ cb) {
    const int b  = blockIdx.y;
    const int l0 = blockIdx.x * 128;
    const int tid = threadIdx.x;
    const int d4 = tid % 96;
    const int rg = tid / 96;
    const int ls = l0 + rg * 32;
    const int d0 = d4 * 4;

    float w0[4], w1[4], w2[4], bb[4];
#pragma unroll
    for (int j = 0; j < 4; j++) {
        w0[j] = __ldg(cw + (d0 + j) * 3 + 0);
        w1[j] = __ldg(cw + (d0 + j) * 3 + 1);
        w2[j] = __ldg(cw + (d0 + j) * 3 + 2);
        bb[j] = __ldg(cb + d0 + j);
    }

    const __nv_bfloat16* base = g_h1 + ((size_t)b * LL) * DIN + d0;
    __nv_bfloat16* obase = g_act + ((size_t)b * LL) * DIN + d0;

    float pv[4] = { 0, 0, 0, 0 }, cv[4], nv[4];
    if (ls != 0) ld4bf(base + (size_t)(ls - 1) * DIN, pv);
    ld4bf(base + (size_t)ls * DIN, cv);

#pragma unroll 4
    for (int i = 0; i < 32; i++) {
        int l = ls + i;
        if (l == LL - 1) { nv[0] = nv[1] = nv[2] = nv[3] = 0.f; }
        else ld4bf(base + (size_t)(l + 1) * DIN, nv);
        float o[4];
#pragma unroll
        for (int j = 0; j < 4; j++) {
            float v = pv[j] * w0[j] + cv[j] * w1[j] + nv[j] * w2[j] + bb[j];
            o[j] = 0.5f * v * (1.f + erff(v * 0.70710678118654752f));
        }
        __nv_bfloat162 q0 = __float22bfloat162_rn(make_float2(o[0], o[1]));
        __nv_bfloat162 q1 = __float22bfloat162_rn(make_float2(o[2], o[3]));
        uint2 st;
        st.x = *reinterpret_cast<unsigned*>(&q0);
        st.y = *reinterpret_cast<unsigned*>(&q1);
        *(uint2*)(obase + (size_t)l * DIN) = st;
#pragma unroll
        for (int j = 0; j < 4; j++) { pv[j] = cv[j]; cv[j] = nv[j]; }
    }
}

// ======================= GEMM2: BM=128 BN=96, 384 thr, 2 CTA/SM ==============
#define G2A_B (128 * GRB)
#define G2B_B (96 * GRB)
#define G2T_B (G2A_B + G2B_B)     // 32256/stage, x2 = 64512

__device__ __forceinline__ void g2_load(const __nv_bfloat16* __restrict__ act,
                                        int m0, int n0, int k0, int tid,
                                        char* smA, char* smB) {
#pragma unroll
    for (int i = 0; i < 3; i++) {
        int q = tid + i * 384;
        if (q < 1024) {
            int row = q >> 3, c8 = q & 7;
            cp16(smA + row * GRB + c8 * 16,
                 act + (size_t)(m0 + row) * DIN + k0 + c8 * 8);
        }
    }
#pragma unroll
    for (int i = 0; i < 2; i++) {
        int q = tid + i * 384;
        int row = q >> 3, c8 = q & 7;
        cp16(smB + row * GRB + c8 * 16,
             g_w2b + (size_t)(n0 + row) * DIN + k0 + c8 * 8);
    }
}

__global__ __launch_bounds__(384, 2) void gemm2_tc(const float* __restrict__ b2,
                                                   const float* __restrict__ x,
                                                   float* __restrict__ out) {
    extern __shared__ char sm2[];
    const int b  = blockIdx.z;
    const int m0 = blockIdx.x * 128;
    const int n0 = blockIdx.y * 96;
    const int tid = threadIdx.x, lane = tid & 31, wid = tid >> 5;
    const int mw = (wid & 3) * 32, nw = (wid >> 2) * 32;
    const __nv_bfloat16* act = g_act + (size_t)b * LL * DIN;
    const unsigned sbase = (unsigned)__cvta_generic_to_shared(sm2);

    const unsigned a_lo = (mw + (lane & 15)) * GRB + ((lane & 16) ? 16 : 0);
    const unsigned b_lo = (nw + (lane & 7) + ((lane & 16) ? 8 : 0)) * GRB
                          + ((lane & 8) ? 16 : 0);

    float c[2][4][4];
#pragma unroll
    for (int im = 0; im < 2; im++)
#pragma unroll
        for (int jn = 0; jn < 4; jn++)
#pragma unroll
            for (int t = 0; t < 4; t++) c[im][jn][t] = 0.f;

    g2_load(act, m0, n0, 0, tid, sm2, sm2 + G2A_B);
    cp_commit();

    const int NS = DIN / 64;   // 6
#pragma unroll 1
    for (int s = 0; s < NS; s++) {
        cp_wait0();
        __syncthreads();
        if (s + 1 < NS) {
            char* An = sm2 + ((s + 1) & 1) * G2T_B;
            g2_load(act, m0, n0, (s + 1) * 64, tid, An, An + G2A_B);
            cp_commit();
        }
        unsigned Au = sbase + (s & 1) * G2T_B;
        unsigned Bu = Au + G2A_B;
#pragma unroll
        for (int kk = 0; kk < 4; kk++) {
            unsigned af[2][4], bf[2][4];
            ldsm4(af[0], Au + a_lo + kk * 32);
            ldsm4(af[1], Au + a_lo + 16 * GRB + kk * 32);
            ldsm4(bf[0], Bu + b_lo + kk * 32);
            ldsm4(bf[1], Bu + b_lo + 16 * GRB + kk * 32);
#pragma unroll
            for (int im = 0; im < 2; im++)
#pragma unroll
                for (int jn = 0; jn < 4; jn++)
                    mma_bf16(c[im][jn], af[im],
                             bf[jn >> 1][(jn & 1) * 2], bf[jn >> 1][(jn & 1) * 2 + 1]);
        }
        __syncthreads();
    }
#pragma unroll
    for (int im = 0; im < 2; im++) {
        int r0 = m0 + mw + im * 16 + (lane >> 2);
#pragma unroll
        for (int jn = 0; jn < 4; jn++) {
            int col = n0 + nw + jn * 8 + 2 * (lane & 3);
            float bx = __ldg(b2 + col), by = __ldg(b2 + col + 1);
            size_t base0 = ((size_t)b * LL + r0) * CC + col;
            size_t base1 = ((size_t)b * LL + r0 + 8) * CC + col;
            float2 x0 = *(const float2*)(x + base0);
            float2 x1 = *(const float2*)(x + base1);
            float2 o0 = { c[im][jn][0] + bx + x0.x, c[im][jn][1] + by + x0.y };
            float2 o1 = { c[im][jn][2] + bx + x1.x, c[im][jn][3] + by + x1.y };
            *(float2*)(out + base0) = o0;
            *(float2*)(out + base1) = o1;
        }
    }
}

// ---------------------------------------------------------------------------
extern "C" void kernel_launch(void* const* d_in, const int* in_sizes, int n_in,
                              void* d_out, int out_size) {
    const float* x      = (const float*)d_in[0];
    const float* norm_w = (const float*)d_in[1];
    const float* norm_b = (const float*)d_in[2];
    const float* sel_w1 = (const float*)d_in[3];
    const float* sel_b1 = (const float*)d_in[4];
    const float* sel_w2 = (const float*)d_in[5];
    const float* sel_b2 = (const float*)d_in[6];
    const float* fc1_w  = (const float*)d_in[7];
    const float* fc1_b  = (const float*)d_in[8];
    const float* conv_w = (const float*)d_in[9];
    const float* conv_b = (const float*)d_in[10];
    const float* fc2_w  = (const float*)d_in[11];
    const float* fc2_b  = (const float*)d_in[12];
    float* out = (float*)d_out;

    cudaFuncSetAttribute(gemm1_tc, cudaFuncAttributeMaxDynamicSharedMemorySize,
                         2 * G1T_B);
    cudaFuncSetAttribute(gemm2_tc, cudaFuncAttributeMaxDynamicSharedMemorySize,
                         2 * G2T_B);

    ln_kernel<<<(BB * LL) / 8, 256>>>(x, norm_w, norm_b);
    sel_kernel<<<BB, 256>>>(sel_w1, sel_b1, sel_w2, sel_b2);
    wcvt_kernel<<<(DIN * CC / 4 + 255) / 256, 256>>>(fc1_w, fc2_w);
    gemm1_tc<<<dim3(LL / 128, DIN / 128, BB), 512, 2 * G1T_B>>>(fc1_b);
    convgelu_kernel<<<dim3(LL / 128, BB), 384>>>(conv_w, conv_b);
    gemm2_tc<<<dim3(LL / 128, CC / 96, BB), 384, 2 * G2T_B>>>(fc2_b, x, out);
}

// round 13
// speedup vs baseline: 1.4837x; 1.0012x over previous
#include <cuda_runtime.h>
#include <cuda_bf16.h>
#include <math.h>

#define BB   32
#define HH   64
#define WW   64
#define CC   192
#define DIN  384
#define LL   4096   // HH*WW

// ---------------- scratch (device globals; no runtime alloc) ----------------
__device__ __nv_bfloat16 g_xn [(size_t)BB * LL * CC];     // layernormed x (bf16)
__device__ float g_gm [BB * LL];                          // per-pixel mean of xn
__device__ int   g_dir[BB];                               // direction per batch
__device__ __nv_bfloat16 g_h1 [(size_t)BB * LL * DIN];    // fc1 output (bf16)
__device__ __nv_bfloat16 g_act[(size_t)BB * LL * DIN];    // gelu(conv(h1)) (bf16)
__device__ __nv_bfloat16 g_w1b[DIN * CC];                 // fc1_w in bf16
__device__ __nv_bfloat16 g_w2b[CC * DIN];                 // fc2_w in bf16

__device__ __forceinline__ void cp16(void* dst, const void* src) {
    unsigned d = (unsigned)__cvta_generic_to_shared(dst);
    asm volatile("cp.async.cg.shared.global [%0], [%1], 16;" :: "r"(d), "l"(src));
}
__device__ __forceinline__ void cp_commit() {
    asm volatile("cp.async.commit_group;");
}
__device__ __forceinline__ void cp_wait0() {
    asm volatile("cp.async.wait_group 0;");
}

__device__ __forceinline__ void ldsm4(unsigned r[4], unsigned addr) {
    asm volatile("ldmatrix.sync.aligned.m8n8.x4.shared.b16 {%0,%1,%2,%3}, [%4];"
                 : "=r"(r[0]), "=r"(r[1]), "=r"(r[2]), "=r"(r[3]) : "r"(addr));
}

__device__ __forceinline__ void mma_bf16(float c[4], const unsigned a[4],
                                         unsigned b0, unsigned b1) {
    asm volatile(
        "mma.sync.aligned.m16n8k16.row.col.f32.bf16.bf16.f32 "
        "{%0,%1,%2,%3}, {%4,%5,%6,%7}, {%8,%9}, {%0,%1,%2,%3};"
        : "+f"(c[0]), "+f"(c[1]), "+f"(c[2]), "+f"(c[3])
        : "r"(a[0]), "r"(a[1]), "r"(a[2]), "r"(a[3]), "r"(b0), "r"(b1));
}

// ---------------------------- 1) LayerNorm (bf16 out) ------------------------
__global__ __launch_bounds__(256) void ln_kernel(const float* __restrict__ x,
                                                 const float* __restrict__ nw,
                                                 const float* __restrict__ nb) {
    int warp = (blockIdx.x * blockDim.x + threadIdx.x) >> 5;
    int lane = threadIdx.x & 31;
    if (warp >= BB * LL) return;
    const float* row = x + (size_t)warp * CC;

    float2 v[3];
    float s = 0.f;
#pragma unroll
    for (int i = 0; i < 3; i++) {
        v[i] = *(const float2*)(row + 2 * lane + 64 * i);
        s += v[i].x + v[i].y;
    }
#pragma unroll
    for (int o = 16; o; o >>= 1) s += __shfl_xor_sync(0xffffffffu, s, o);
    float mu = s * (1.f / CC);

    float q = 0.f;
#pragma unroll
    for (int i = 0; i < 3; i++) {
        float dx = v[i].x - mu, dy = v[i].y - mu;
        q += dx * dx + dy * dy;
    }
#pragma unroll
    for (int o = 16; o; o >>= 1) q += __shfl_xor_sync(0xffffffffu, q, o);
    float rsig = rsqrtf(q * (1.f / CC) + 1e-5f);

    float xs = 0.f;
    __nv_bfloat16* dst = g_xn + (size_t)warp * CC;
#pragma unroll
    for (int i = 0; i < 3; i++) {
        int c = 2 * lane + 64 * i;
        float ax = (v[i].x - mu) * rsig * nw[c] + nb[c];
        float ay = (v[i].y - mu) * rsig * nw[c + 1] + nb[c + 1];
        *(__nv_bfloat162*)(dst + c) = __float22bfloat162_rn(make_float2(ax, ay));
        xs += ax + ay;
    }
#pragma unroll
    for (int o = 16; o; o >>= 1) xs += __shfl_xor_sync(0xffffffffu, xs, o);
    if (lane == 0) g_gm[warp] = xs * (1.f / CC);
}

// ---------------------------- 2) Direction selector --------------------------
__device__ __forceinline__ int refl(int k) {
    return (k == 0) ? 1 : ((k == 65) ? 62 : (k - 1));
}

__global__ __launch_bounds__(256) void sel_kernel(const float* __restrict__ w1,
                                                  const float* __restrict__ b1,
                                                  const float* __restrict__ w2,
                                                  const float* __restrict__ b2) {
    __shared__ float sg[LL];
    __shared__ float red[256];
    __shared__ float sh_s;
    int b = blockIdx.x;
    int tid = threadIdx.x;
    for (int i = tid; i < LL; i += 256) sg[i] = g_gm[b * LL + i];
    __syncthreads();

    float ssh = 0.f;
    for (int t = tid; t < 66 * 64; t += 256) {
        int r = t >> 6, j = t & 63;
        int rr = refl(r);
        ssh += fabsf(sg[rr * 64 + refl(j + 2)] - sg[rr * 64 + refl(j)]);
    }
    float ssv = 0.f;
    for (int t = tid; t < 64 * 66; t += 256) {
        int i = t / 66, c = t % 66;
        int cc = refl(c);
        ssv += fabsf(sg[refl(i + 2) * 64 + cc] - sg[refl(i) * 64 + cc]);
    }

    red[tid] = ssh; __syncthreads();
    for (int s = 128; s > 0; s >>= 1) { if (tid < s) red[tid] += red[tid + s]; __syncthreads(); }
    if (tid == 0) sh_s = red[0] * (1.f / 4224.f);
    __syncthreads();
    red[tid] = ssv; __syncthreads();
    for (int s = 128; s > 0; s >>= 1) { if (tid < s) red[tid] += red[tid + s]; __syncthreads(); }
    if (tid == 0) {
        float sh = sh_s, sv = red[0] * (1.f / 4224.f);
        float sc[4] = { sh, sv, 0.5f * (sh + sv), fabsf(sh - sv) };
        float hid[16];
#pragma unroll
        for (int j = 0; j < 16; j++) {
            float a = b1[j];
#pragma unroll
            for (int k = 0; k < 4; k++) a += sc[k] * w1[j * 4 + k];
            hid[j] = fmaxf(a, 0.f);
        }
        int best = 0; float bv = -1e30f;
#pragma unroll
        for (int i = 0; i < 4; i++) {
            float a = b2[i];
#pragma unroll
            for (int j = 0; j < 16; j++) a += hid[j] * w2[i * 16 + j];
            if (a > bv) { bv = a; best = i; }
        }
        g_dir[b] = best;
    }
}

// -------------------- 2b) weights fp32 -> bf16 prep --------------------------
__global__ __launch_bounds__(256) void wcvt_kernel(const float* __restrict__ w1,
                                                   const float* __restrict__ w2) {
    int i = (blockIdx.x * blockDim.x + threadIdx.x) * 4;
    if (i >= DIN * CC) return;
    {
        float4 v = *(const float4*)(w1 + i);
        *(__nv_bfloat162*)(g_w1b + i) = __float22bfloat162_rn(make_float2(v.x, v.y));
        *(__nv_bfloat162*)(g_w1b + i + 2) = __float22bfloat162_rn(make_float2(v.z, v.w));
    }
    {
        float4 v = *(const float4*)(w2 + i);
        *(__nv_bfloat162*)(g_w2b + i) = __float22bfloat162_rn(make_float2(v.x, v.y));
        *(__nv_bfloat162*)(g_w2b + i + 2) = __float22bfloat162_rn(make_float2(v.z, v.w));
    }
}

// ---------------- GEMM geometry: row stride 144B, BK=64, 2-stage -------------
#define GRB 144

// ==== GEMM1: BM=128 BN=128, 256 thr (8 warps 2x4, warp tile 64x32), 2 CTA/SM =
#define G1A_B (128 * GRB)
#define G1B_B (128 * GRB)
#define G1T_B (G1A_B + G1B_B)     // 36864/stage, x2 = 73728

__device__ __forceinline__ void g1_load(const __nv_bfloat16* __restrict__ xnb,
                                        int m0, int n0, int k0, int dir,
                                        int tid, char* smA, char* smB) {
#pragma unroll
    for (int i = 0; i < 4; i++) {
        int q = tid + i * 256;
        int row = q >> 3, c8 = q & 7;
        int l = m0 + row;
        int pix;
        if (dir == 0)      pix = l;
        else if (dir == 3) pix = ((l & 63) << 6) + 63 - (l >> 6);
        else               pix = ((l & 63) << 6) + (l >> 6);
        cp16(smA + row * GRB + c8 * 16, xnb + (size_t)pix * CC + k0 + c8 * 8);
    }
#pragma unroll
    for (int i = 0; i < 4; i++) {
        int q = tid + i * 256;
        int row = q >> 3, c8 = q & 7;
        cp16(smB + row * GRB + c8 * 16, g_w1b + (size_t)(n0 + row) * CC + k0 + c8 * 8);
    }
}

__global__ __launch_bounds__(256, 2) void gemm1_tc(const float* __restrict__ b1) {
    extern __shared__ char sm1[];
    const int b  = blockIdx.z;
    const int m0 = blockIdx.x * 128;
    const int n0 = blockIdx.y * 128;
    const int dir = g_dir[b];
    const int tid = threadIdx.x, lane = tid & 31, wid = tid >> 5;
    const int mw = (wid & 1) * 64, nw = (wid >> 1) * 32;
    const __nv_bfloat16* xnb = g_xn + (size_t)b * LL * CC;
    const unsigned sbase = (unsigned)__cvta_generic_to_shared(sm1);

    const unsigned a_lo = (mw + (lane & 15)) * GRB + ((lane & 16) ? 16 : 0);
    const unsigned b_lo = (nw + (lane & 7) + ((lane & 16) ? 8 : 0)) * GRB
                          + ((lane & 8) ? 16 : 0);

    float c[4][4][4];
#pragma unroll
    for (int im = 0; im < 4; im++)
#pragma unroll
        for (int jn = 0; jn < 4; jn++)
#pragma unroll
            for (int t = 0; t < 4; t++) c[im][jn][t] = 0.f;

    g1_load(xnb, m0, n0, 0, dir, tid, sm1, sm1 + G1A_B);
    cp_commit();

    const int NS = CC / 64;   // 3
#pragma unroll 1
    for (int s = 0; s < NS; s++) {
        cp_wait0();
        __syncthreads();
        if (s + 1 < NS) {
            char* An = sm1 + ((s + 1) & 1) * G1T_B;
            g1_load(xnb, m0, n0, (s + 1) * 64, dir, tid, An, An + G1A_B);
            cp_commit();
        }
        unsigned Au = sbase + (s & 1) * G1T_B;
        unsigned Bu = Au + G1A_B;
#pragma unroll
        for (int kk = 0; kk < 4; kk++) {
            unsigned af[4][4], bf[2][4];
#pragma unroll
            for (int i = 0; i < 4; i++)
                ldsm4(af[i], Au + a_lo + i * 16 * GRB + kk * 32);
#pragma unroll
            for (int j = 0; j < 2; j++)
                ldsm4(bf[j], Bu + b_lo + j * 16 * GRB + kk * 32);
#pragma unroll
            for (int im = 0; im < 4; im++)
#pragma unroll
                for (int jn = 0; jn < 4; jn++)
                    mma_bf16(c[im][jn], af[im],
                             bf[jn >> 1][(jn & 1) * 2], bf[jn >> 1][(jn & 1) * 2 + 1]);
        }
        __syncthreads();
    }
#pragma unroll
    for (int im = 0; im < 4; im++) {
        int r0 = m0 + mw + im * 16 + (lane >> 2);
#pragma unroll
        for (int jn = 0; jn < 4; jn++) {
            int col = n0 + nw + jn * 8 + 2 * (lane & 3);
            float bx = __ldg(b1 + col), by = __ldg(b1 + col + 1);
            __nv_bfloat162 o0 = __float22bfloat162_rn(
                make_float2(c[im][jn][0] + bx, c[im][jn][1] + by));
            __nv_bfloat162 o1 = __float22bfloat162_rn(
                make_float2(c[im][jn][2] + bx, c[im][jn][3] + by));
            *(__nv_bfloat162*)(g_h1 + ((size_t)b * LL + r0) * DIN + col) = o0;
            *(__nv_bfloat162*)(g_h1 + ((size_t)b * LL + r0 + 8) * DIN + col) = o1;
        }
    }
}

// ---------------------------- 4) depthwise conv3 + GELU (bf16 io) -----------
__device__ __forceinline__ void ld4bf(const __nv_bfloat16* p, float v[4]) {
    uint2 u = *(const uint2*)p;
    float2 a = __bfloat1622float2(*reinterpret_cast<__nv_bfloat162*>(&u.x));
    float2 b = __bfloat1622float2(*reinterpret_cast<__nv_bfloat162*>(&u.y));
    v[0] = a.x; v[1] = a.y; v[2] = b.x; v[3] = b.y;
}

__global__ __launch_bounds__(384) void convgelu_kernel(const float* __restrict__ cw,
                                                       const float* __restrict__ cb) {
    const int b  = blockIdx.y;
    const int l0 = blockIdx.x * 128;
    const int tid = threadIdx.x;
    const int d4 = tid % 96;
    const int rg = tid / 96;
    const int ls = l0 + rg * 32;
    const int d0 = d4 * 4;

    float w0[4], w1[4], w2[4], bb[4];
#pragma unroll
    for (int j = 0; j < 4; j++) {
        w0[j] = __ldg(cw + (d0 + j) * 3 + 0);
        w1[j] = __ldg(cw + (d0 + j) * 3 + 1);
        w2[j] = __ldg(cw + (d0 + j) * 3 + 2);
        bb[j] = __ldg(cb + d0 + j);
    }

    const __nv_bfloat16* base = g_h1 + ((size_t)b * LL) * DIN + d0;
    __nv_bfloat16* obase = g_act + ((size_t)b * LL) * DIN + d0;

    float pv[4] = { 0, 0, 0, 0 }, cv[4], nv[4];
    if (ls != 0) ld4bf(base + (size_t)(ls - 1) * DIN, pv);
    ld4bf(base + (size_t)ls * DIN, cv);

#pragma unroll 4
    for (int i = 0; i < 32; i++) {
        int l = ls + i;
        if (l == LL - 1) { nv[0] = nv[1] = nv[2] = nv[3] = 0.f; }
        else ld4bf(base + (size_t)(l + 1) * DIN, nv);
        float o[4];
#pragma unroll
        for (int j = 0; j < 4; j++) {
            float v = pv[j] * w0[j] + cv[j] * w1[j] + nv[j] * w2[j] + bb[j];
            o[j] = 0.5f * v * (1.f + erff(v * 0.70710678118654752f));
        }
        __nv_bfloat162 q0 = __float22bfloat162_rn(make_float2(o[0], o[1]));
        __nv_bfloat162 q1 = __float22bfloat162_rn(make_float2(o[2], o[3]));
        uint2 st;
        st.x = *reinterpret_cast<unsigned*>(&q0);
        st.y = *reinterpret_cast<unsigned*>(&q1);
        *(uint2*)(obase + (size_t)l * DIN) = st;
#pragma unroll
        for (int j = 0; j < 4; j++) { pv[j] = cv[j]; cv[j] = nv[j]; }
    }
}

// ==== GEMM2: BM=128 BN=96, 192 thr (6 warps 2x3, warp tile 64x32), 3 CTA/SM ==
#define G2A_B (128 * GRB)
#define G2B_B (96 * GRB)
#define G2T_B (G2A_B + G2B_B)     // 32256/stage, x2 = 64512

__device__ __forceinline__ void g2_load(const __nv_bfloat16* __restrict__ act,
                                        int m0, int n0, int k0, int tid,
                                        char* smA, char* smB) {
#pragma unroll
    for (int i = 0; i < 6; i++) {
        int q = tid + i * 192;
        if (q < 1024) {
            int row = q >> 3, c8 = q & 7;
            cp16(smA + row * GRB + c8 * 16,
                 act + (size_t)(m0 + row) * DIN + k0 + c8 * 8);
        }
    }
#pragma unroll
    for (int i = 0; i < 4; i++) {
        int q = tid + i * 192;
        int row = q >> 3, c8 = q & 7;
        cp16(smB + row * GRB + c8 * 16,
             g_w2b + (size_t)(n0 + row) * DIN + k0 + c8 * 8);
    }
}

__global__ __launch_bounds__(192, 3) void gemm2_tc(const float* __restrict__ b2,
                                                   const float* __restrict__ x,
                                                   float* __restrict__ out) {
    extern __shared__ char sm2[];
    const int b  = blockIdx.z;
    const int m0 = blockIdx.x * 128;
    const int n0 = blockIdx.y * 96;
    const int tid = threadIdx.x, lane = tid & 31, wid = tid >> 5;
    const int mw = (wid & 1) * 64, nw = (wid >> 1) * 32;
    const __nv_bfloat16* act = g_act + (size_t)b * LL * DIN;
    const unsigned sbase = (unsigned)__cvta_generic_to_shared(sm2);

    const unsigned a_lo = (mw + (lane & 15)) * GRB + ((lane & 16) ? 16 : 0);
    const unsigned b_lo = (nw + (lane & 7) + ((lane & 16) ? 8 : 0)) * GRB
                          + ((lane & 8) ? 16 : 0);

    float c[4][4][4];
#pragma unroll
    for (int im = 0; im < 4; im++)
#pragma unroll
        for (int jn = 0; jn < 4; jn++)
#pragma unroll
            for (int t = 0; t < 4; t++) c[im][jn][t] = 0.f;

    g2_load(act, m0, n0, 0, tid, sm2, sm2 + G2A_B);
    cp_commit();

    const int NS = DIN / 64;   // 6
#pragma unroll 1
    for (int s = 0; s < NS; s++) {
        cp_wait0();
        __syncthreads();
        if (s + 1 < NS) {
            char* An = sm2 + ((s + 1) & 1) * G2T_B;
            g2_load(act, m0, n0, (s + 1) * 64, tid, An, An + G2A_B);
            cp_commit();
        }
        unsigned Au = sbase + (s & 1) * G2T_B;
        unsigned Bu = Au + G2A_B;
#pragma unroll
        for (int kk = 0; kk < 4; kk++) {
            unsigned af[4][4], bf[2][4];
#pragma unroll
            for (int i = 0; i < 4; i++)
                ldsm4(af[i], Au + a_lo + i * 16 * GRB + kk * 32);
#pragma unroll
            for (int j = 0; j < 2; j++)
                ldsm4(bf[j], Bu + b_lo + j * 16 * GRB + kk * 32);
#pragma unroll
            for (int im = 0; im < 4; im++)
#pragma unroll
                for (int jn = 0; jn < 4; jn++)
                    mma_bf16(c[im][jn], af[im],
                             bf[jn >> 1][(jn & 1) * 2], bf[jn >> 1][(jn & 1) * 2 + 1]);
        }
        __syncthreads();
    }
#pragma unroll
    for (int im = 0; im < 4; im++) {
        int r0 = m0 + mw + im * 16 + (lane >> 2);
#pragma unroll
        for (int jn = 0; jn < 4; jn++) {
            int col = n0 + nw + jn * 8 + 2 * (lane & 3);
            float bx = __ldg(b2 + col), by = __ldg(b2 + col + 1);
            size_t base0 = ((size_t)b * LL + r0) * CC + col;
            size_t base1 = ((size_t)b * LL + r0 + 8) * CC + col;
            float2 x0 = *(const float2*)(x + base0);
            float2 x1 = *(const float2*)(x + base1);
            float2 o0 = { c[im][jn][0] + bx + x0.x, c[im][jn][1] + by + x0.y };
            float2 o1 = { c[im][jn][2] + bx + x1.x, c[im][jn][3] + by + x1.y };
            *(float2*)(out + base0) = o0;
            *(float2*)(out + base1) = o1;
        }
    }
}

// ---------------------------------------------------------------------------
extern "C" void kernel_launch(void* const* d_in, const int* in_sizes, int n_in,
                              void* d_out, int out_size) {
    const float* x      = (const float*)d_in[0];
    const float* norm_w = (const float*)d_in[1];
    const float* norm_b = (const float*)d_in[2];
    const float* sel_w1 = (const float*)d_in[3];
    const float* sel_b1 = (const float*)d_in[4];
    const float* sel_w2 = (const float*)d_in[5];
    const float* sel_b2 = (const float*)d_in[6];
    const float* fc1_w  = (const float*)d_in[7];
    const float* fc1_b  = (const float*)d_in[8];
    const float* conv_w = (const float*)d_in[9];
    const float* conv_b = (const float*)d_in[10];
    const float* fc2_w  = (const float*)d_in[11];
    const float* fc2_b  = (const float*)d_in[12];
    float* out = (float*)d_out;

    cudaFuncSetAttribute(gemm1_tc, cudaFuncAttributeMaxDynamicSharedMemorySize,
                         2 * G1T_B);
    cudaFuncSetAttribute(gemm2_tc, cudaFuncAttributeMaxDynamicSharedMemorySize,
                         2 * G2T_B);

    ln_kernel<<<(BB * LL) / 8, 256>>>(x, norm_w, norm_b);
    sel_kernel<<<BB, 256>>>(sel_w1, sel_b1, sel_w2, sel_b2);
    wcvt_kernel<<<(DIN * CC / 4 + 255) / 256, 256>>>(fc1_w, fc2_w);
    gemm1_tc<<<dim3(LL / 128, DIN / 128, BB), 256, 2 * G1T_B>>>(fc1_b);
    convgelu_kernel<<<dim3(LL / 128, BB), 384>>>(conv_w, conv_b);
    gemm2_tc<<<dim3(LL / 128, CC / 96, BB), 192, 2 * G2T_B>>>(fc2_b, x, out);
}

// round 14
// speedup vs baseline: 1.5331x; 1.0333x over previous
#include <cuda_runtime.h>
#include <cuda_bf16.h>
#include <math.h>

#define BB   32
#define HH   64
#define WW   64
#define CC   192
#define DIN  384
#define LL   4096   // HH*WW

// ---------------- scratch (device globals; no runtime alloc) ----------------
__device__ __nv_bfloat16 g_xn [(size_t)BB * LL * CC];     // layernormed x (bf16)
__device__ float g_gm [BB * LL];                          // per-pixel mean of xn
__device__ int   g_dir[BB];                               // direction per batch
__device__ __nv_bfloat16 g_h1 [(size_t)BB * LL * DIN];    // fc1 output (bf16)
__device__ __nv_bfloat16 g_act[(size_t)BB * LL * DIN];    // gelu(conv(h1)) (bf16)
__device__ __nv_bfloat16 g_w1b[DIN * CC];                 // fc1_w in bf16
__device__ __nv_bfloat16 g_w2b[CC * DIN];                 // fc2_w in bf16

__device__ __forceinline__ void cp16(void* dst, const void* src) {
    unsigned d = (unsigned)__cvta_generic_to_shared(dst);
    asm volatile("cp.async.cg.shared.global [%0], [%1], 16;" :: "r"(d), "l"(src));
}
__device__ __forceinline__ void cp_commit() {
    asm volatile("cp.async.commit_group;");
}
__device__ __forceinline__ void cp_wait0() {
    asm volatile("cp.async.wait_group 0;");
}
__device__ __forceinline__ void cp_wait1() {
    asm volatile("cp.async.wait_group 1;");
}

__device__ __forceinline__ void ldsm4(unsigned r[4], unsigned addr) {
    asm volatile("ldmatrix.sync.aligned.m8n8.x4.shared.b16 {%0,%1,%2,%3}, [%4];"
                 : "=r"(r[0]), "=r"(r[1]), "=r"(r[2]), "=r"(r[3]) : "r"(addr));
}

__device__ __forceinline__ void mma_bf16(float c[4], const unsigned a[4],
                                         unsigned b0, unsigned b1) {
    asm volatile(
        "mma.sync.aligned.m16n8k16.row.col.f32.bf16.bf16.f32 "
        "{%0,%1,%2,%3}, {%4,%5,%6,%7}, {%8,%9}, {%0,%1,%2,%3};"
        : "+f"(c[0]), "+f"(c[1]), "+f"(c[2]), "+f"(c[3])
        : "r"(a[0]), "r"(a[1]), "r"(a[2]), "r"(a[3]), "r"(b0), "r"(b1));
}

// ---------------------------- 1) LayerNorm (bf16 out) ------------------------
__global__ __launch_bounds__(256) void ln_kernel(const float* __restrict__ x,
                                                 const float* __restrict__ nw,
                                                 const float* __restrict__ nb) {
    int warp = (blockIdx.x * blockDim.x + threadIdx.x) >> 5;
    int lane = threadIdx.x & 31;
    if (warp >= BB * LL) return;
    const float* row = x + (size_t)warp * CC;

    float2 v[3];
    float s = 0.f;
#pragma unroll
    for (int i = 0; i < 3; i++) {
        v[i] = *(const float2*)(row + 2 * lane + 64 * i);
        s += v[i].x + v[i].y;
    }
#pragma unroll
    for (int o = 16; o; o >>= 1) s += __shfl_xor_sync(0xffffffffu, s, o);
    float mu = s * (1.f / CC);

    float q = 0.f;
#pragma unroll
    for (int i = 0; i < 3; i++) {
        float dx = v[i].x - mu, dy = v[i].y - mu;
        q += dx * dx + dy * dy;
    }
#pragma unroll
    for (int o = 16; o; o >>= 1) q += __shfl_xor_sync(0xffffffffu, q, o);
    float rsig = rsqrtf(q * (1.f / CC) + 1e-5f);

    float xs = 0.f;
    __nv_bfloat16* dst = g_xn + (size_t)warp * CC;
#pragma unroll
    for (int i = 0; i < 3; i++) {
        int c = 2 * lane + 64 * i;
        float ax = (v[i].x - mu) * rsig * nw[c] + nb[c];
        float ay = (v[i].y - mu) * rsig * nw[c + 1] + nb[c + 1];
        *(__nv_bfloat162*)(dst + c) = __float22bfloat162_rn(make_float2(ax, ay));
        xs += ax + ay;
    }
#pragma unroll
    for (int o = 16; o; o >>= 1) xs += __shfl_xor_sync(0xffffffffu, xs, o);
    if (lane == 0) g_gm[warp] = xs * (1.f / CC);
}

// ---------------------------- 2) Direction selector --------------------------
__device__ __forceinline__ int refl(int k) {
    return (k == 0) ? 1 : ((k == 65) ? 62 : (k - 1));
}

__global__ __launch_bounds__(256) void sel_kernel(const float* __restrict__ w1,
                                                  const float* __restrict__ b1,
                                                  const float* __restrict__ w2,
                                                  const float* __restrict__ b2) {
    __shared__ float sg[LL];
    __shared__ float red[256];
    __shared__ float sh_s;
    int b = blockIdx.x;
    int tid = threadIdx.x;
    for (int i = tid; i < LL; i += 256) sg[i] = g_gm[b * LL + i];
    __syncthreads();

    float ssh = 0.f;
    for (int t = tid; t < 66 * 64; t += 256) {
        int r = t >> 6, j = t & 63;
        int rr = refl(r);
        ssh += fabsf(sg[rr * 64 + refl(j + 2)] - sg[rr * 64 + refl(j)]);
    }
    float ssv = 0.f;
    for (int t = tid; t < 64 * 66; t += 256) {
        int i = t / 66, c = t % 66;
        int cc = refl(c);
        ssv += fabsf(sg[refl(i + 2) * 64 + cc] - sg[refl(i) * 64 + cc]);
    }

    red[tid] = ssh; __syncthreads();
    for (int s = 128; s > 0; s >>= 1) { if (tid < s) red[tid] += red[tid + s]; __syncthreads(); }
    if (tid == 0) sh_s = red[0] * (1.f / 4224.f);
    __syncthreads();
    red[tid] = ssv; __syncthreads();
    for (int s = 128; s > 0; s >>= 1) { if (tid < s) red[tid] += red[tid + s]; __syncthreads(); }
    if (tid == 0) {
        float sh = sh_s, sv = red[0] * (1.f / 4224.f);
        float sc[4] = { sh, sv, 0.5f * (sh + sv), fabsf(sh - sv) };
        float hid[16];
#pragma unroll
        for (int j = 0; j < 16; j++) {
            float a = b1[j];
#pragma unroll
            for (int k = 0; k < 4; k++) a += sc[k] * w1[j * 4 + k];
            hid[j] = fmaxf(a, 0.f);
        }
        int best = 0; float bv = -1e30f;
#pragma unroll
        for (int i = 0; i < 4; i++) {
            float a = b2[i];
#pragma unroll
            for (int j = 0; j < 16; j++) a += hid[j] * w2[i * 16 + j];
            if (a > bv) { bv = a; best = i; }
        }
        g_dir[b] = best;
    }
}

// -------------------- 2b) weights fp32 -> bf16 prep --------------------------
__global__ __launch_bounds__(256) void wcvt_kernel(const float* __restrict__ w1,
                                                   const float* __restrict__ w2) {
    int i = (blockIdx.x * blockDim.x + threadIdx.x) * 4;
    if (i >= DIN * CC) return;
    {
        float4 v = *(const float4*)(w1 + i);
        *(__nv_bfloat162*)(g_w1b + i) = __float22bfloat162_rn(make_float2(v.x, v.y));
        *(__nv_bfloat162*)(g_w1b + i + 2) = __float22bfloat162_rn(make_float2(v.z, v.w));
    }
    {
        float4 v = *(const float4*)(w2 + i);
        *(__nv_bfloat162*)(g_w2b + i) = __float22bfloat162_rn(make_float2(v.x, v.y));
        *(__nv_bfloat162*)(g_w2b + i + 2) = __float22bfloat162_rn(make_float2(v.z, v.w));
    }
}

// ---------------- GEMM geometry: row stride 144B, BK=64 ----------------------
#define GRB 144

// == GEMM1: BM=128 BN=128, 256 thr (8 warps 2x4, tile 64x32), 3-stage, 2 CTA ==
#define G1A_B (128 * GRB)
#define G1B_B (128 * GRB)
#define G1T_B (G1A_B + G1B_B)     // 36864/stage, x3 = 110592

__device__ __forceinline__ void g1_load(const __nv_bfloat16* __restrict__ xnb,
                                        int m0, int n0, int k0, int dir,
                                        int tid, char* smA, char* smB) {
#pragma unroll
    for (int i = 0; i < 4; i++) {
        int q = tid + i * 256;
        int row = q >> 3, c8 = q & 7;
        int l = m0 + row;
        int pix;
        if (dir == 0)      pix = l;
        else if (dir == 3) pix = ((l & 63) << 6) + 63 - (l >> 6);
        else               pix = ((l & 63) << 6) + (l >> 6);
        cp16(smA + row * GRB + c8 * 16, xnb + (size_t)pix * CC + k0 + c8 * 8);
    }
#pragma unroll
    for (int i = 0; i < 4; i++) {
        int q = tid + i * 256;
        int row = q >> 3, c8 = q & 7;
        cp16(smB + row * GRB + c8 * 16, g_w1b + (size_t)(n0 + row) * CC + k0 + c8 * 8);
    }
}

__global__ __launch_bounds__(256, 2) void gemm1_tc(const float* __restrict__ b1) {
    extern __shared__ char sm1[];
    const int b  = blockIdx.z;
    const int m0 = blockIdx.x * 128;
    const int n0 = blockIdx.y * 128;
    const int dir = g_dir[b];
    const int tid = threadIdx.x, lane = tid & 31, wid = tid >> 5;
    const int mw = (wid & 1) * 64, nw = (wid >> 1) * 32;
    const __nv_bfloat16* xnb = g_xn + (size_t)b * LL * CC;
    const unsigned sbase = (unsigned)__cvta_generic_to_shared(sm1);

    const unsigned a_lo = (mw + (lane & 15)) * GRB + ((lane & 16) ? 16 : 0);
    const unsigned b_lo = (nw + (lane & 7) + ((lane & 16) ? 8 : 0)) * GRB
                          + ((lane & 8) ? 16 : 0);

    float c[4][4][4];
#pragma unroll
    for (int im = 0; im < 4; im++)
#pragma unroll
        for (int jn = 0; jn < 4; jn++)
#pragma unroll
            for (int t = 0; t < 4; t++) c[im][jn][t] = 0.f;

    // 3 stages cover all of K=192: no buffer reuse, prefetch 2 up-front
    g1_load(xnb, m0, n0, 0, dir, tid, sm1, sm1 + G1A_B);
    cp_commit();
    g1_load(xnb, m0, n0, 64, dir, tid, sm1 + G1T_B, sm1 + G1T_B + G1A_B);
    cp_commit();

    const int NS = CC / 64;   // 3
#pragma unroll 1
    for (int s = 0; s < NS; s++) {
        if (s == NS - 1) cp_wait0(); else cp_wait1();
        __syncthreads();
        if (s == 0) {
            char* An = sm1 + 2 * G1T_B;
            g1_load(xnb, m0, n0, 128, dir, tid, An, An + G1A_B);
            cp_commit();
        }
        unsigned Au = sbase + s * G1T_B;
        unsigned Bu = Au + G1A_B;
#pragma unroll
        for (int kk = 0; kk < 4; kk++) {
            unsigned af[4][4], bf[2][4];
#pragma unroll
            for (int i = 0; i < 4; i++)
                ldsm4(af[i], Au + a_lo + i * 16 * GRB + kk * 32);
#pragma unroll
            for (int j = 0; j < 2; j++)
                ldsm4(bf[j], Bu + b_lo + j * 16 * GRB + kk * 32);
#pragma unroll
            for (int im = 0; im < 4; im++)
#pragma unroll
                for (int jn = 0; jn < 4; jn++)
                    mma_bf16(c[im][jn], af[im],
                             bf[jn >> 1][(jn & 1) * 2], bf[jn >> 1][(jn & 1) * 2 + 1]);
        }
    }
#pragma unroll
    for (int im = 0; im < 4; im++) {
        int r0 = m0 + mw + im * 16 + (lane >> 2);
#pragma unroll
        for (int jn = 0; jn < 4; jn++) {
            int col = n0 + nw + jn * 8 + 2 * (lane & 3);
            float bx = __ldg(b1 + col), by = __ldg(b1 + col + 1);
            __nv_bfloat162 o0 = __float22bfloat162_rn(
                make_float2(c[im][jn][0] + bx, c[im][jn][1] + by));
            __nv_bfloat162 o1 = __float22bfloat162_rn(
                make_float2(c[im][jn][2] + bx, c[im][jn][3] + by));
            *(__nv_bfloat162*)(g_h1 + ((size_t)b * LL + r0) * DIN + col) = o0;
            *(__nv_bfloat162*)(g_h1 + ((size_t)b * LL + r0 + 8) * DIN + col) = o1;
        }
    }
}

// ------------------ 4) depthwise conv3 + GELU (bf16 io, 8 ch/thread) --------
__device__ __forceinline__ void ld8bf(const __nv_bfloat16* p, float v[8]) {
    uint4 u = *(const uint4*)p;
    float2 a = __bfloat1622float2(*reinterpret_cast<__nv_bfloat162*>(&u.x));
    float2 b = __bfloat1622float2(*reinterpret_cast<__nv_bfloat162*>(&u.y));
    float2 c = __bfloat1622float2(*reinterpret_cast<__nv_bfloat162*>(&u.z));
    float2 d = __bfloat1622float2(*reinterpret_cast<__nv_bfloat162*>(&u.w));
    v[0] = a.x; v[1] = a.y; v[2] = b.x; v[3] = b.y;
    v[4] = c.x; v[5] = c.y; v[6] = d.x; v[7] = d.y;
}

__global__ __launch_bounds__(384) void convgelu_kernel(const float* __restrict__ cw,
                                                       const float* __restrict__ cb) {
    const int b  = blockIdx.y;
    const int l0 = blockIdx.x * 128;
    const int tid = threadIdx.x;
    const int d8 = tid % 48;           // 48 channel-groups of 8
    const int rg = tid / 48;           // 8 row-groups of 16
    const int ls = l0 + rg * 16;
    const int d0 = d8 * 8;

    float w0[8], w1[8], w2[8], bb[8];
#pragma unroll
    for (int t = 0; t < 6; t++) {
        float4 f = __ldg((const float4*)(cw + d0 * 3) + t);
        float* wf = (t & 1) ? nullptr : nullptr;
        // unpack interleaved (ch*3 layout): handled below
        ((float*)w0)[0] = 0.f; // placeholder removed after unpack
        (void)wf; (void)f;
    }
    // conv_w layout: [ch][3]; load 24 floats for channels d0..d0+7
    {
        float wv[24];
#pragma unroll
        for (int t = 0; t < 6; t++) {
            float4 f = __ldg((const float4*)(cw + d0 * 3) + t);
            wv[t * 4 + 0] = f.x; wv[t * 4 + 1] = f.y;
            wv[t * 4 + 2] = f.z; wv[t * 4 + 3] = f.w;
        }
#pragma unroll
        for (int j = 0; j < 8; j++) {
            w0[j] = wv[j * 3 + 0];
            w1[j] = wv[j * 3 + 1];
            w2[j] = wv[j * 3 + 2];
        }
#pragma unroll
        for (int t = 0; t < 2; t++) {
            float4 f = __ldg((const float4*)(cb + d0) + t);
            bb[t * 4 + 0] = f.x; bb[t * 4 + 1] = f.y;
            bb[t * 4 + 2] = f.z; bb[t * 4 + 3] = f.w;
        }
    }

    const __nv_bfloat16* base = g_h1 + ((size_t)b * LL) * DIN + d0;
    __nv_bfloat16* obase = g_act + ((size_t)b * LL) * DIN + d0;

    float pv[8] = {0,0,0,0,0,0,0,0}, cv[8], nv[8];
    if (ls != 0) ld8bf(base + (size_t)(ls - 1) * DIN, pv);
    ld8bf(base + (size_t)ls * DIN, cv);

#pragma unroll 2
    for (int i = 0; i < 16; i++) {
        int l = ls + i;
        if (l == LL - 1) {
#pragma unroll
            for (int j = 0; j < 8; j++) nv[j] = 0.f;
        } else {
            ld8bf(base + (size_t)(l + 1) * DIN, nv);
        }
        unsigned o[4];
#pragma unroll
        for (int j = 0; j < 4; j++) {
            float v0 = pv[2*j] * w0[2*j] + cv[2*j] * w1[2*j]
                     + nv[2*j] * w2[2*j] + bb[2*j];
            float v1 = pv[2*j+1] * w0[2*j+1] + cv[2*j+1] * w1[2*j+1]
                     + nv[2*j+1] * w2[2*j+1] + bb[2*j+1];
            float g0 = 0.5f * v0 * (1.f + erff(v0 * 0.70710678118654752f));
            float g1 = 0.5f * v1 * (1.f + erff(v1 * 0.70710678118654752f));
            __nv_bfloat162 q = __float22bfloat162_rn(make_float2(g0, g1));
            o[j] = *reinterpret_cast<unsigned*>(&q);
        }
        *(uint4*)(obase + (size_t)l * DIN) = make_uint4(o[0], o[1], o[2], o[3]);
#pragma unroll
        for (int j = 0; j < 8; j++) { pv[j] = cv[j]; cv[j] = nv[j]; }
    }
}

// == GEMM2: BM=128 BN=96, 384 thr (12 warps 4x3, tile 32x32), 3-stage, 2 CTA ==
#define G2A_B (128 * GRB)
#define G2B_B (96 * GRB)
#define G2T_B (G2A_B + G2B_B)     // 32256/stage, x3 = 96768

__device__ __forceinline__ void g2_load(const __nv_bfloat16* __restrict__ act,
                                        int m0, int n0, int k0, int tid,
                                        char* smA, char* smB) {
#pragma unroll
    for (int i = 0; i < 3; i++) {
        int q = tid + i * 384;
        if (q < 1024) {
            int row = q >> 3, c8 = q & 7;
            cp16(smA + row * GRB + c8 * 16,
                 act + (size_t)(m0 + row) * DIN + k0 + c8 * 8);
        }
    }
#pragma unroll
    for (int i = 0; i < 2; i++) {
        int q = tid + i * 384;
        int row = q >> 3, c8 = q & 7;
        cp16(smB + row * GRB + c8 * 16,
             g_w2b + (size_t)(n0 + row) * DIN + k0 + c8 * 8);
    }
}

__global__ __launch_bounds__(384, 2) void gemm2_tc(const float* __restrict__ b2,
                                                   const float* __restrict__ x,
                                                   float* __restrict__ out) {
    extern __shared__ char sm2[];
    const int b  = blockIdx.z;
    const int m0 = blockIdx.x * 128;
    const int n0 = blockIdx.y * 96;
    const int tid = threadIdx.x, lane = tid & 31, wid = tid >> 5;
    const int mw = (wid & 3) * 32, nw = (wid >> 2) * 32;
    const __nv_bfloat16* act = g_act + (size_t)b * LL * DIN;
    const unsigned sbase = (unsigned)__cvta_generic_to_shared(sm2);

    const unsigned a_lo = (mw + (lane & 15)) * GRB + ((lane & 16) ? 16 : 0);
    const unsigned b_lo = (nw + (lane & 7) + ((lane & 16) ? 8 : 0)) * GRB
                          + ((lane & 8) ? 16 : 0);

    float c[2][4][4];
#pragma unroll
    for (int im = 0; im < 2; im++)
#pragma unroll
        for (int jn = 0; jn < 4; jn++)
#pragma unroll
            for (int t = 0; t < 4; t++) c[im][jn][t] = 0.f;

    g2_load(act, m0, n0, 0, tid, sm2, sm2 + G2A_B);
    cp_commit();
    g2_load(act, m0, n0, 64, tid, sm2 + G2T_B, sm2 + G2T_B + G2A_B);
    cp_commit();

    const int NS = DIN / 64;   // 6
#pragma unroll 1
    for (int s = 0; s < NS; s++) {
        if (s + 1 < NS) cp_wait1(); else cp_wait0();
        __syncthreads();
        if (s + 2 < NS) {
            char* An = sm2 + ((s + 2) % 3) * G2T_B;
            g2_load(act, m0, n0, (s + 2) * 64, tid, An, An + G2A_B);
            cp_commit();
        }
        unsigned Au = sbase + (s % 3) * G2T_B;
        unsigned Bu = Au + G2A_B;
#pragma unroll
        for (int kk = 0; kk < 4; kk++) {
            unsigned af[2][4], bf[2][4];
            ldsm4(af[0], Au + a_lo + kk * 32);
            ldsm4(af[1], Au + a_lo + 16 * GRB + kk * 32);
            ldsm4(bf[0], Bu + b_lo + kk * 32);
            ldsm4(bf[1], Bu + b_lo + 16 * GRB + kk * 32);
#pragma unroll
            for (int im = 0; im < 2; im++)
#pragma unroll
                for (int jn = 0; jn < 4; jn++)
                    mma_bf16(c[im][jn], af[im],
                             bf[jn >> 1][(jn & 1) * 2], bf[jn >> 1][(jn & 1) * 2 + 1]);
        }
    }
#pragma unroll
    for (int im = 0; im < 2; im++) {
        int r0 = m0 + mw + im * 16 + (lane >> 2);
#pragma unroll
        for (int jn = 0; jn < 4; jn++) {
            int col = n0 + nw + jn * 8 + 2 * (lane & 3);
            float bx = __ldg(b2 + col), by = __ldg(b2 + col + 1);
            size_t base0 = ((size_t)b * LL + r0) * CC + col;
            size_t base1 = ((size_t)b * LL + r0 + 8) * CC + col;
            float2 x0 = *(const float2*)(x + base0);
            float2 x1 = *(const float2*)(x + base1);
            float2 o0 = { c[im][jn][0] + bx + x0.x, c[im][jn][1] + by + x0.y };
            float2 o1 = { c[im][jn][2] + bx + x1.x, c[im][jn][3] + by + x1.y };
            *(float2*)(out + base0) = o0;
            *(float2*)(out + base1) = o1;
        }
    }
}

// ---------------------------------------------------------------------------
extern "C" void kernel_launch(void* const* d_in, const int* in_sizes, int n_in,
                              void* d_out, int out_size) {
    const float* x      = (const float*)d_in[0];
    const float* norm_w = (const float*)d_in[1];
    const float* norm_b = (const float*)d_in[2];
    const float* sel_w1 = (const float*)d_in[3];
    const float* sel_b1 = (const float*)d_in[4];
    const float* sel_w2 = (const float*)d_in[5];
    const float* sel_b2 = (const float*)d_in[6];
    const float* fc1_w  = (const float*)d_in[7];
    const float* fc1_b  = (const float*)d_in[8];
    const float* conv_w = (const float*)d_in[9];
    const float* conv_b = (const float*)d_in[10];
    const float* fc2_w  = (const float*)d_in[11];
    const float* fc2_b  = (const float*)d_in[12];
    float* out = (float*)d_out;

    cudaFuncSetAttribute(gemm1_tc, cudaFuncAttributeMaxDynamicSharedMemorySize,
                         3 * G1T_B);
    cudaFuncSetAttribute(gemm2_tc, cudaFuncAttributeMaxDynamicSharedMemorySize,
                         3 * G2T_B);

    ln_kernel<<<(BB * LL) / 8, 256>>>(x, norm_w, norm_b);
    sel_kernel<<<BB, 256>>>(sel_w1, sel_b1, sel_w2, sel_b2);
    wcvt_kernel<<<(DIN * CC / 4 + 255) / 256, 256>>>(fc1_w, fc2_w);
    gemm1_tc<<<dim3(LL / 128, DIN / 128, BB), 256, 3 * G1T_B>>>(fc1_b);
    convgelu_kernel<<<dim3(LL / 128, BB), 384>>>(conv_w, conv_b);
    gemm2_tc<<<dim3(LL / 128, CC / 96, BB), 384, 3 * G2T_B>>>(fc2_b, x, out);
}